// round 1
// baseline (speedup 1.0000x reference)
#include <cuda_runtime.h>
#include <cuda_bf16.h>

// Problem constants
#define B_  2
#define S_  2048
#define D_  512
#define H_  8
#define HD_ 64
#define T_  (B_*S_)      // 4096 tokens
#define FF_ (4*D_)       // 2048

// Scratch (device globals; no allocation allowed)
__device__ float g_xn[T_*D_];     // layernorm output (reused for ln2)
__device__ float g_q[T_*D_];      // [B,H,S,HD]
__device__ float g_k[T_*D_];
__device__ float g_v[T_*D_];
__device__ float g_attn[T_*D_];   // attention out, concat layout [B,S,D]
__device__ float g_h[T_*FF_];     // MLP hidden

// ---------------------------------------------------------------------------
// LayerNorm: one block per token row, 256 threads, D=512 (2 elems/thread)
// ---------------------------------------------------------------------------
__global__ void ln_kernel(const float* __restrict__ x, const float* __restrict__ g,
                          const float* __restrict__ be, float* __restrict__ out) {
    int row = blockIdx.x;
    int t = threadIdx.x;
    const float* xr = x + row * D_;
    float v0 = xr[t], v1 = xr[t + 256];
    float s = v0 + v1, ss = v0 * v0 + v1 * v1;
#pragma unroll
    for (int o = 16; o > 0; o >>= 1) {
        s  += __shfl_xor_sync(0xffffffffu, s, o);
        ss += __shfl_xor_sync(0xffffffffu, ss, o);
    }
    __shared__ float rs[8], rss[8];
    if ((t & 31) == 0) { rs[t >> 5] = s; rss[t >> 5] = ss; }
    __syncthreads();
    s = 0.f; ss = 0.f;
#pragma unroll
    for (int i = 0; i < 8; i++) { s += rs[i]; ss += rss[i]; }
    float mean = s * (1.f / (float)D_);
    float var  = ss * (1.f / (float)D_) - mean * mean;
    float r = rsqrtf(var + 1e-5f);
    out[row * D_ + t]       = (v0 - mean) * r * g[t]       + be[t];
    out[row * D_ + t + 256] = (v1 - mean) * r * g[t + 256] + be[t + 256];
}

// ---------------------------------------------------------------------------
// Fused per-head QKV GEMM. grid = (T/64, H), 256 threads, BM=64,BN=64,BK=16.
// A tile (xn) loaded once, reused for Wq/Wk/Wv. Outputs in [B,H,S,HD] layout.
// ---------------------------------------------------------------------------
__global__ void qkv_kernel(const float* __restrict__ A,
                           const float* __restrict__ Wq, const float* __restrict__ bq,
                           const float* __restrict__ Wk, const float* __restrict__ bk,
                           const float* __restrict__ Wv, const float* __restrict__ bv,
                           float* __restrict__ Q, float* __restrict__ Ko,
                           float* __restrict__ V) {
    __shared__ float As[16 * 68];
    __shared__ float Bqs[16 * 64], Bks[16 * 64], Bvs[16 * 64];
    int tid = threadIdx.x, tx = tid & 15, ty = tid >> 4;
    int h = blockIdx.y;
    int m0 = blockIdx.x * 64;
    const float* wq = Wq + h * D_ * HD_;
    const float* wk = Wk + h * D_ * HD_;
    const float* wv = Wv + h * D_ * HD_;

    float aq[4][4] = {}, akk[4][4] = {}, avv[4][4] = {};
    int am = tid >> 2, akcol = (tid & 3) * 4;

    for (int k0 = 0; k0 < D_; k0 += 16) {
        float4 a4 = *(const float4*)(A + (m0 + am) * D_ + k0 + akcol);
        As[(akcol + 0) * 68 + am] = a4.x;
        As[(akcol + 1) * 68 + am] = a4.y;
        As[(akcol + 2) * 68 + am] = a4.z;
        As[(akcol + 3) * 68 + am] = a4.w;
        *(float4*)(Bqs + ty * 64 + tx * 4) = *(const float4*)(wq + (k0 + ty) * HD_ + tx * 4);
        *(float4*)(Bks + ty * 64 + tx * 4) = *(const float4*)(wk + (k0 + ty) * HD_ + tx * 4);
        *(float4*)(Bvs + ty * 64 + tx * 4) = *(const float4*)(wv + (k0 + ty) * HD_ + tx * 4);
        __syncthreads();
#pragma unroll
        for (int kk = 0; kk < 16; kk++) {
            float4 a = *(const float4*)(As + kk * 68 + ty * 4);
            float4 bq4 = *(const float4*)(Bqs + kk * 64 + tx * 4);
            float4 bk4 = *(const float4*)(Bks + kk * 64 + tx * 4);
            float4 bv4 = *(const float4*)(Bvs + kk * 64 + tx * 4);
            float aa[4] = {a.x, a.y, a.z, a.w};
            float qb[4] = {bq4.x, bq4.y, bq4.z, bq4.w};
            float kb[4] = {bk4.x, bk4.y, bk4.z, bk4.w};
            float vb[4] = {bv4.x, bv4.y, bv4.z, bv4.w};
#pragma unroll
            for (int u = 0; u < 4; u++)
#pragma unroll
                for (int w = 0; w < 4; w++) {
                    aq[u][w]  += aa[u] * qb[w];
                    akk[u][w] += aa[u] * kb[w];
                    avv[u][w] += aa[u] * vb[w];
                }
        }
        __syncthreads();
    }
#pragma unroll
    for (int u = 0; u < 4; u++) {
        int t = m0 + ty * 4 + u;
        int bb = t >> 11;          // t / S_
        int s = t & (S_ - 1);
        int base = ((bb * H_ + h) * S_ + s) * HD_;
#pragma unroll
        for (int w = 0; w < 4; w++) {
            int e = tx * 4 + w;
            Q[base + e]  = aq[u][w]  + bq[h * HD_ + e];
            Ko[base + e] = akk[u][w] + bk[h * HD_ + e];
            V[base + e]  = avv[u][w] + bv[h * HD_ + e];
        }
    }
}

// ---------------------------------------------------------------------------
// Flash attention. grid = (S/64, B*H), 256 threads (16x16), Q-tile 64 rows,
// KV-tile 64, HD=64. Online softmax; P tile reuses K's smem region.
// ---------------------------------------------------------------------------
#define FLASH_SMEM_FLOATS (64*64 + 64*65 + 64*65)
__global__ void flash_kernel(const float* __restrict__ Q, const float* __restrict__ K,
                             const float* __restrict__ V, float* __restrict__ O) {
    extern __shared__ float sm[];
    float* Qs = sm;                 // [64][64]
    float* Ks = sm + 64 * 64;       // [64][65] (later reused as P)
    float* Vs = Ks + 64 * 65;       // [64][65]

    int tid = threadIdx.x, tx = tid & 15, ty = tid >> 4;
    int bh = blockIdx.y;
    int q0 = blockIdx.x * 64;
    const float* Qb = Q + (bh * S_ + q0) * HD_;
    const float* Kb = K + bh * S_ * HD_;
    const float* Vb = V + bh * S_ * HD_;

    // load Q tile (linear copy, layouts identical)
#pragma unroll
    for (int r = 0; r < 4; r++) {
        int idx = (r * 256 + tid) * 4;
        *(float4*)(Qs + idx) = *(const float4*)(Qb + idx);
    }

    float m[4], l[4], o[4][4];
#pragma unroll
    for (int u = 0; u < 4; u++) {
        m[u] = -1e30f; l[u] = 0.f;
#pragma unroll
        for (int w = 0; w < 4; w++) o[u][w] = 0.f;
    }

    for (int kv = 0; kv < S_; kv += 64) {
        // load K,V tiles: stride-65 rows; vector LDG + scalar STS
#pragma unroll
        for (int r = 0; r < 4; r++) {
            int idx4 = r * 256 + tid;            // 0..1023
            int c = idx4 >> 4;                   // row 0..63
            int i = (idx4 & 15) * 4;             // col 0..60
            float4 k4 = *(const float4*)(Kb + (kv + c) * HD_ + i);
            float4 v4 = *(const float4*)(Vb + (kv + c) * HD_ + i);
            Ks[c * 65 + i + 0] = k4.x; Ks[c * 65 + i + 1] = k4.y;
            Ks[c * 65 + i + 2] = k4.z; Ks[c * 65 + i + 3] = k4.w;
            Vs[c * 65 + i + 0] = v4.x; Vs[c * 65 + i + 1] = v4.y;
            Vs[c * 65 + i + 2] = v4.z; Vs[c * 65 + i + 3] = v4.w;
        }
        __syncthreads();

        // S = Q * K^T  (64x64), 4x4 microtile per thread
        float acc[4][4] = {};
#pragma unroll 8
        for (int i = 0; i < 64; i++) {
            float a[4], b[4];
#pragma unroll
            for (int u = 0; u < 4; u++) a[u] = Qs[(ty * 4 + u) * 64 + i];
#pragma unroll
            for (int w = 0; w < 4; w++) b[w] = Ks[(tx * 4 + w) * 65 + i];
#pragma unroll
            for (int u = 0; u < 4; u++)
#pragma unroll
                for (int w = 0; w < 4; w++) acc[u][w] += a[u] * b[w];
        }

        // online softmax per row (16 lanes share a row: same ty)
#pragma unroll
        for (int u = 0; u < 4; u++) {
            float rmax = fmaxf(fmaxf(acc[u][0], acc[u][1]), fmaxf(acc[u][2], acc[u][3]));
#pragma unroll
            for (int off = 8; off > 0; off >>= 1)
                rmax = fmaxf(rmax, __shfl_xor_sync(0xffffffffu, rmax, off));
            float mn = fmaxf(m[u], rmax);
            float corr = __expf(m[u] - mn);
            float ps = 0.f;
#pragma unroll
            for (int w = 0; w < 4; w++) {
                acc[u][w] = __expf(acc[u][w] - mn);
                ps += acc[u][w];
            }
#pragma unroll
            for (int off = 8; off > 0; off >>= 1)
                ps += __shfl_xor_sync(0xffffffffu, ps, off);
            l[u] = l[u] * corr + ps;
            m[u] = mn;
#pragma unroll
            for (int w = 0; w < 4; w++) o[u][w] *= corr;
        }
        __syncthreads();   // everyone done reading Ks before overwrite with P

        // write P into Ks region
#pragma unroll
        for (int u = 0; u < 4; u++)
#pragma unroll
            for (int w = 0; w < 4; w++)
                Ks[(ty * 4 + u) * 65 + tx * 4 + w] = acc[u][w];
        __syncthreads();

        // O += P * V
#pragma unroll 8
        for (int c = 0; c < 64; c++) {
            float a[4], b[4];
#pragma unroll
            for (int u = 0; u < 4; u++) a[u] = Ks[(ty * 4 + u) * 65 + c];
#pragma unroll
            for (int w = 0; w < 4; w++) b[w] = Vs[c * 65 + tx * 4 + w];
#pragma unroll
            for (int u = 0; u < 4; u++)
#pragma unroll
                for (int w = 0; w < 4; w++) o[u][w] += a[u] * b[w];
        }
        __syncthreads();   // before next tile load overwrites Ks/Vs
    }

    // write out in concat layout [B,S,D]
    int b_ = bh >> 3, h = bh & 7;
#pragma unroll
    for (int u = 0; u < 4; u++) {
        float inv = 1.f / l[u];
        int s = q0 + ty * 4 + u;
#pragma unroll
        for (int w = 0; w < 4; w++)
            O[(b_ * S_ + s) * D_ + h * HD_ + tx * 4 + w] = o[u][w] * inv;
    }
}

// ---------------------------------------------------------------------------
// Generic GEMM: C[M,N] = act(A[M,K] @ W[K,N] + bias) (+ res). 64x64x16 tiles.
// grid = (N/64, M/64), 256 threads, 4x4 microtile.
// ---------------------------------------------------------------------------
template <bool RELU, bool RES>
__global__ void gemm_kernel(const float* __restrict__ A, const float* __restrict__ W,
                            const float* __restrict__ bias, const float* __restrict__ res,
                            float* __restrict__ C, int M, int N, int K) {
    __shared__ float As[16 * 68];
    __shared__ float Bs[16 * 64];
    int tid = threadIdx.x, tx = tid & 15, ty = tid >> 4;
    int m0 = blockIdx.y * 64, n0 = blockIdx.x * 64;
    float acc[4][4] = {};
    int am = tid >> 2, ak = (tid & 3) * 4;

    for (int k0 = 0; k0 < K; k0 += 16) {
        float4 a4 = *(const float4*)(A + (m0 + am) * K + k0 + ak);
        As[(ak + 0) * 68 + am] = a4.x;
        As[(ak + 1) * 68 + am] = a4.y;
        As[(ak + 2) * 68 + am] = a4.z;
        As[(ak + 3) * 68 + am] = a4.w;
        *(float4*)(Bs + ty * 64 + tx * 4) = *(const float4*)(W + (k0 + ty) * N + n0 + tx * 4);
        __syncthreads();
#pragma unroll
        for (int kk = 0; kk < 16; kk++) {
            float4 a = *(const float4*)(As + kk * 68 + ty * 4);
            float4 b = *(const float4*)(Bs + kk * 64 + tx * 4);
            float aa[4] = {a.x, a.y, a.z, a.w};
            float bb[4] = {b.x, b.y, b.z, b.w};
#pragma unroll
            for (int u = 0; u < 4; u++)
#pragma unroll
                for (int w = 0; w < 4; w++) acc[u][w] += aa[u] * bb[w];
        }
        __syncthreads();
    }
#pragma unroll
    for (int u = 0; u < 4; u++) {
        int mrow = m0 + ty * 4 + u;
#pragma unroll
        for (int w = 0; w < 4; w++) {
            int ncol = n0 + tx * 4 + w;
            float v = acc[u][w] + bias[ncol];
            if (RELU) v = fmaxf(v, 0.f);
            if (RES)  v += res[mrow * N + ncol];
            C[mrow * N + ncol] = v;
        }
    }
}

// ---------------------------------------------------------------------------
// Launch
// ---------------------------------------------------------------------------
extern "C" void kernel_launch(void* const* d_in, const int* in_sizes, int n_in,
                              void* d_out, int out_size) {
    const float* x   = (const float*)d_in[0];
    const float* Wq  = (const float*)d_in[1];
    const float* bq  = (const float*)d_in[2];
    const float* Wk  = (const float*)d_in[3];
    const float* bk  = (const float*)d_in[4];
    const float* Wv  = (const float*)d_in[5];
    const float* bv  = (const float*)d_in[6];
    const float* Wp  = (const float*)d_in[7];
    const float* bp  = (const float*)d_in[8];
    const float* W1  = (const float*)d_in[9];
    const float* b1  = (const float*)d_in[10];
    const float* W2  = (const float*)d_in[11];
    const float* b2  = (const float*)d_in[12];
    const float* g1  = (const float*)d_in[13];
    const float* be1 = (const float*)d_in[14];
    const float* g2  = (const float*)d_in[15];
    const float* be2 = (const float*)d_in[16];
    float* out = (float*)d_out;

    float *xn, *q, *k, *v, *attn, *hbuf;
    cudaGetSymbolAddress((void**)&xn,   g_xn);
    cudaGetSymbolAddress((void**)&q,    g_q);
    cudaGetSymbolAddress((void**)&k,    g_k);
    cudaGetSymbolAddress((void**)&v,    g_v);
    cudaGetSymbolAddress((void**)&attn, g_attn);
    cudaGetSymbolAddress((void**)&hbuf, g_h);

    // 1) LN1
    ln_kernel<<<T_, 256>>>(x, g1, be1, xn);

    // 2) fused QKV
    qkv_kernel<<<dim3(T_ / 64, H_), 256>>>(xn, Wq, bq, Wk, bk, Wv, bv, q, k, v);

    // 3) flash attention
    static int smem_set = 0;
    if (!smem_set) {
        cudaFuncSetAttribute(flash_kernel, cudaFuncAttributeMaxDynamicSharedMemorySize,
                             FLASH_SMEM_FLOATS * (int)sizeof(float));
        smem_set = 1;
    }
    flash_kernel<<<dim3(S_ / 64, B_ * H_), 256, FLASH_SMEM_FLOATS * sizeof(float)>>>(q, k, v, attn);

    // 4) proj + residual: out = x + attn @ Wp + bp
    gemm_kernel<false, true><<<dim3(D_ / 64, T_ / 64), 256>>>(attn, Wp, bp, x, out, T_, D_, D_);

    // 5) LN2
    ln_kernel<<<T_, 256>>>(out, g2, be2, xn);

    // 6) MLP1 (ReLU)
    gemm_kernel<true, false><<<dim3(FF_ / 64, T_ / 64), 256>>>(xn, W1, b1, nullptr, hbuf, T_, FF_, D_);

    // 7) MLP2 + residual (in place on out)
    gemm_kernel<false, true><<<dim3(D_ / 64, T_ / 64), 256>>>(hbuf, W2, b2, out, out, T_, D_, FF_);
}

// round 4
// speedup vs baseline: 1.4594x; 1.4594x over previous
#include <cuda_runtime.h>
#include <cuda_bf16.h>
#include <cstdint>

// Problem constants
#define B_  2
#define S_  2048
#define D_  512
#define H_  8
#define HD_ 64
#define T_  (B_*S_)      // 4096 tokens
#define FF_ (4*D_)       // 2048
#define QKV_N (3*D_)     // 1536

typedef __nv_bfloat16 bf16;

// ---------------------------------------------------------------------------
// Scratch (device globals; no allocation allowed)
// ---------------------------------------------------------------------------
__device__ bf16 g_xn_hi[T_*D_], g_xn_lo[T_*D_];             // LN out
__device__ float g_qkv[(size_t)T_*QKV_N];                   // fused QKV fp32 [T,1536]
__device__ bf16 g_attn_hi[T_*D_], g_attn_lo[T_*D_];         // attention out [B,S,D]
__device__ bf16 g_h_hi[(size_t)T_*FF_], g_h_lo[(size_t)T_*FF_]; // MLP hidden
__device__ float g_bqkv[QKV_N];
// transposed+split weights: layout [N, K] bf16
__device__ bf16 g_wqkv_hi[QKV_N*D_], g_wqkv_lo[QKV_N*D_];
__device__ bf16 g_wp_hi[D_*D_], g_wp_lo[D_*D_];
__device__ bf16 g_w1_hi[D_*FF_], g_w1_lo[D_*FF_];
__device__ bf16 g_w2_hi[D_*FF_], g_w2_lo[D_*FF_];

// ---------------------------------------------------------------------------
// helpers
// ---------------------------------------------------------------------------
__device__ __forceinline__ uint32_t smem_to_u32(const void* p) {
    uint32_t a;
    asm("{ .reg .u64 tmp; cvta.to.shared.u64 tmp, %1; cvt.u32.u64 %0, tmp; }"
        : "=r"(a) : "l"(p));
    return a;
}
__device__ __forceinline__ void ldsm_x4(uint32_t* r, uint32_t addr) {
    asm volatile("ldmatrix.sync.aligned.m8n8.x4.shared.b16 {%0,%1,%2,%3}, [%4];"
        : "=r"(r[0]), "=r"(r[1]), "=r"(r[2]), "=r"(r[3]) : "r"(addr));
}
__device__ __forceinline__ void mma16816(float* c, const uint32_t* a, const uint32_t* b) {
    asm volatile("mma.sync.aligned.m16n8k16.row.col.f32.bf16.bf16.f32 "
        "{%0,%1,%2,%3}, {%4,%5,%6,%7}, {%8,%9}, {%0,%1,%2,%3};"
        : "+f"(c[0]), "+f"(c[1]), "+f"(c[2]), "+f"(c[3])
        : "r"(a[0]), "r"(a[1]), "r"(a[2]), "r"(a[3]), "r"(b[0]), "r"(b[1]));
}
__device__ __forceinline__ void split_bf16(float v, bf16& h, bf16& l) {
    h = __float2bfloat16(v);
    l = __float2bfloat16(v - __bfloat162float(h));
}
// swizzled byte offset within a 128row x 64B tile (rows of 4 x 16B groups)
__device__ __forceinline__ uint32_t sw_off(int row, int g) {
    return (uint32_t)(((row << 2) | (g ^ ((row >> 1) & 3))) << 4);
}

// ---------------------------------------------------------------------------
// Weight conversion kernels
// ---------------------------------------------------------------------------
// transpose [K,N] fp32 -> [N,K] bf16 hi/lo
__global__ void convw_t(const float* __restrict__ W, bf16* __restrict__ hi,
                        bf16* __restrict__ lo, int K, int N) {
    __shared__ float t[32][33];
    int kb = blockIdx.x * 32, nb = blockIdx.y * 32;
    int tx = threadIdx.x, ty = threadIdx.y;     // 32 x 8
#pragma unroll
    for (int i = 0; i < 32; i += 8) t[ty + i][tx] = W[(size_t)(kb + ty + i) * N + nb + tx];
    __syncthreads();
#pragma unroll
    for (int i = 0; i < 32; i += 8) {
        float v = t[tx][ty + i];
        size_t o = (size_t)(nb + ty + i) * K + kb + tx;
        bf16 h, l; split_bf16(v, h, l);
        hi[o] = h; lo[o] = l;
    }
}
// QKV weights [H, D, HD] -> [N=H*HD, K=D]
__global__ void convw_qkv(const float* __restrict__ W, bf16* __restrict__ hi,
                          bf16* __restrict__ lo) {
    __shared__ float t[32][33];
    int h = blockIdx.z;
    int db = blockIdx.x * 32, eb = blockIdx.y * 32;
    const float* base = W + (size_t)h * D_ * HD_;
    int tx = threadIdx.x, ty = threadIdx.y;
#pragma unroll
    for (int i = 0; i < 32; i += 8) t[ty + i][tx] = base[(size_t)(db + ty + i) * HD_ + eb + tx];
    __syncthreads();
#pragma unroll
    for (int i = 0; i < 32; i += 8) {
        float v = t[tx][ty + i];
        int n = h * HD_ + eb + ty + i, k = db + tx;
        bf16 hh, ll; split_bf16(v, hh, ll);
        hi[(size_t)n * D_ + k] = hh; lo[(size_t)n * D_ + k] = ll;
    }
}
__global__ void pack_bias(const float* __restrict__ bq, const float* __restrict__ bk,
                          const float* __restrict__ bv, float* __restrict__ o) {
    int t = blockIdx.x * 256 + threadIdx.x;
    if (t < D_) { o[t] = bq[t]; o[t + D_] = bk[t]; o[t + 2 * D_] = bv[t]; }
}

// ---------------------------------------------------------------------------
// LayerNorm -> bf16 hi/lo pair. One block per row, 256 threads.
// ---------------------------------------------------------------------------
__global__ void ln_kernel(const float* __restrict__ x, const float* __restrict__ g,
                          const float* __restrict__ be, bf16* __restrict__ hi,
                          bf16* __restrict__ lo) {
    int row = blockIdx.x;
    int t = threadIdx.x;
    const float* xr = x + (size_t)row * D_;
    float v0 = xr[t], v1 = xr[t + 256];
    float s = v0 + v1, ss = v0 * v0 + v1 * v1;
#pragma unroll
    for (int o = 16; o > 0; o >>= 1) {
        s  += __shfl_xor_sync(0xffffffffu, s, o);
        ss += __shfl_xor_sync(0xffffffffu, ss, o);
    }
    __shared__ float rs[8], rss[8];
    if ((t & 31) == 0) { rs[t >> 5] = s; rss[t >> 5] = ss; }
    __syncthreads();
    s = 0.f; ss = 0.f;
#pragma unroll
    for (int i = 0; i < 8; i++) { s += rs[i]; ss += rss[i]; }
    float mean = s * (1.f / (float)D_);
    float var  = ss * (1.f / (float)D_) - mean * mean;
    float r = rsqrtf(var + 1e-5f);
    float y0 = (v0 - mean) * r * g[t] + be[t];
    float y1 = (v1 - mean) * r * g[t + 256] + be[t + 256];
    bf16 h, l;
    split_bf16(y0, h, l); hi[(size_t)row * D_ + t] = h;       lo[(size_t)row * D_ + t] = l;
    split_bf16(y1, h, l); hi[(size_t)row * D_ + t + 256] = h; lo[(size_t)row * D_ + t + 256] = l;
}

// ---------------------------------------------------------------------------
// mma.sync GEMM with bf16x3 compensation.
// C[M,N] = act(Ahi/lo[M,K] @ (Bhi/lo[N,K])^T + bias) (+res)
// CTA tile 128x128, BK=32; 8 warps as 2(m) x 4(n), warp tile 64x32.
// B fragments use NON-transposed ldmatrix: B is [N,K] K-contiguous, which
// matches the mma row.col B-fragment layout (lane = n*4 + k/2) directly.
// ---------------------------------------------------------------------------
#define SMT_AHI 0
#define SMT_ALO 8192
#define SMT_BHI 16384
#define SMT_BLO 24576

template <bool RELU, bool RES, bool OUTPAIR>
__global__ void __launch_bounds__(256, 2) mma_gemm(
    const bf16* __restrict__ Ahi, const bf16* __restrict__ Alo,
    const bf16* __restrict__ Bhi, const bf16* __restrict__ Blo,
    const float* __restrict__ bias, const float* __restrict__ res,
    float* __restrict__ Cf, bf16* __restrict__ Chi, bf16* __restrict__ Clo,
    int M, int N, int K) {
    __shared__ __align__(128) char smem_buf[32768];
    uint32_t sb = smem_to_u32(smem_buf);
    int tid = threadIdx.x, lane = tid & 31, wid = tid >> 5;
    int wm = wid >> 2, wn = wid & 3;
    int m0 = blockIdx.y * 128, n0 = blockIdx.x * 128;

    float acc[4][4][4];
#pragma unroll
    for (int a = 0; a < 4; a++)
#pragma unroll
        for (int b = 0; b < 4; b++)
#pragma unroll
            for (int cc = 0; cc < 4; cc++) acc[a][b][cc] = 0.f;

    int ldrow = tid >> 2, ldg_ = tid & 3;          // 64 rows per 256-thread pass
    int nchunk = K >> 5;
    for (int c = 0; c < nchunk; c++) {
        int k0 = c << 5;
#pragma unroll
        for (int it = 0; it < 2; it++) {
            int row = ldrow + it * 64;
            uint32_t off = sw_off(row, ldg_);
            size_t ao = (size_t)(m0 + row) * K + k0 + ldg_ * 8;
            size_t bo = (size_t)(n0 + row) * K + k0 + ldg_ * 8;
            *(float4*)(smem_buf + SMT_AHI + off) = *(const float4*)(Ahi + ao);
            *(float4*)(smem_buf + SMT_ALO + off) = *(const float4*)(Alo + ao);
            *(float4*)(smem_buf + SMT_BHI + off) = *(const float4*)(Bhi + bo);
            *(float4*)(smem_buf + SMT_BLO + off) = *(const float4*)(Blo + bo);
        }
        __syncthreads();
#pragma unroll
        for (int ks = 0; ks < 2; ks++) {
            int kg = ks * 2;
            // B fragments: 4 n-tiles; non-trans ldmatrix.x4:
            // lanes 0-7 -> (n 0-7, kg), 8-15 -> (n 0-7, kg+1),
            // lanes 16-23 -> (n 8-15, kg), 24-31 -> (n 8-15, kg+1)
            uint32_t bh[4][2], bl[4][2];
#pragma unroll
            for (int ntp = 0; ntp < 2; ntp++) {
                int nrow = wn * 32 + ntp * 16 + (lane & 7) + ((lane >> 4) & 1) * 8;
                int bg = kg + ((lane >> 3) & 1);
                uint32_t off = sw_off(nrow, bg);
                uint32_t t4[4];
                ldsm_x4(t4, sb + SMT_BHI + off);
                bh[ntp * 2][0] = t4[0]; bh[ntp * 2][1] = t4[1];
                bh[ntp * 2 + 1][0] = t4[2]; bh[ntp * 2 + 1][1] = t4[3];
                ldsm_x4(t4, sb + SMT_BLO + off);
                bl[ntp * 2][0] = t4[0]; bl[ntp * 2][1] = t4[1];
                bl[ntp * 2 + 1][0] = t4[2]; bl[ntp * 2 + 1][1] = t4[3];
            }
#pragma unroll
            for (int mt = 0; mt < 4; mt++) {
                int arow = wm * 64 + mt * 16 + (lane & 7) + ((lane >> 3) & 1) * 8;
                int ag = kg + (lane >> 4);
                uint32_t off = sw_off(arow, ag);
                uint32_t ah[4], al[4];
                ldsm_x4(ah, sb + SMT_AHI + off);
                ldsm_x4(al, sb + SMT_ALO + off);
#pragma unroll
                for (int nt = 0; nt < 4; nt++) {
                    mma16816(acc[mt][nt], ah, bh[nt]);
                    mma16816(acc[mt][nt], ah, bl[nt]);
                    mma16816(acc[mt][nt], al, bh[nt]);
                }
            }
        }
        __syncthreads();
    }

    // epilogue: c0,c1 -> (r, col..col+1), c2,c3 -> (r+8, ...)
#pragma unroll
    for (int mt = 0; mt < 4; mt++) {
#pragma unroll
        for (int nt = 0; nt < 4; nt++) {
            int r0 = m0 + wm * 64 + mt * 16 + (lane >> 2);
            int col = n0 + wn * 32 + nt * 8 + (lane & 3) * 2;
            float b0 = __ldg(bias + col), b1 = __ldg(bias + col + 1);
            float v00 = acc[mt][nt][0] + b0, v01 = acc[mt][nt][1] + b1;
            float v10 = acc[mt][nt][2] + b0, v11 = acc[mt][nt][3] + b1;
            if (RELU) {
                v00 = fmaxf(v00, 0.f); v01 = fmaxf(v01, 0.f);
                v10 = fmaxf(v10, 0.f); v11 = fmaxf(v11, 0.f);
            }
            if (OUTPAIR) {
                bf16 h, l;
                __nv_bfloat162 ph, pl;
                split_bf16(v00, h, l); ph.x = h; pl.x = l;
                split_bf16(v01, h, l); ph.y = h; pl.y = l;
                *(__nv_bfloat162*)(Chi + (size_t)r0 * N + col) = ph;
                *(__nv_bfloat162*)(Clo + (size_t)r0 * N + col) = pl;
                split_bf16(v10, h, l); ph.x = h; pl.x = l;
                split_bf16(v11, h, l); ph.y = h; pl.y = l;
                *(__nv_bfloat162*)(Chi + (size_t)(r0 + 8) * N + col) = ph;
                *(__nv_bfloat162*)(Clo + (size_t)(r0 + 8) * N + col) = pl;
            } else {
                if (RES) {
                    float2 ra = *(const float2*)(res + (size_t)r0 * N + col);
                    float2 rb = *(const float2*)(res + (size_t)(r0 + 8) * N + col);
                    v00 += ra.x; v01 += ra.y; v10 += rb.x; v11 += rb.y;
                }
                float2 o0 = {v00, v01}, o1 = {v10, v11};
                *(float2*)(Cf + (size_t)r0 * N + col) = o0;
                *(float2*)(Cf + (size_t)(r0 + 8) * N + col) = o1;
            }
        }
    }
}

// ---------------------------------------------------------------------------
// Flash attention (fp32 SIMT). QKV fused buffer [T, 1536]; q at +0, k at +512,
// v at +1024 per row. Output: bf16 hi/lo [B,S,D].
// ---------------------------------------------------------------------------
#define QLD QKV_N
#define FLASH_SMEM_FLOATS (64*64 + 64*65 + 64*65)
__global__ void flash_kernel(const float* __restrict__ QKV, bf16* __restrict__ Ohi,
                             bf16* __restrict__ Olo) {
    extern __shared__ float sm[];
    float* Qs = sm;
    float* Ks = sm + 64 * 64;       // reused as P
    float* Vs = Ks + 64 * 65;

    int tid = threadIdx.x, tx = tid & 15, ty = tid >> 4;
    int bh = blockIdx.y;
    int b_ = bh >> 3, h = bh & 7;
    int q0 = blockIdx.x * 64;
    const float* Qb = QKV + ((size_t)b_ * S_ + q0) * QLD + h * HD_;
    const float* Kb = QKV + (size_t)b_ * S_ * QLD + D_ + h * HD_;
    const float* Vb = QKV + (size_t)b_ * S_ * QLD + 2 * D_ + h * HD_;

#pragma unroll
    for (int r = 0; r < 4; r++) {
        int idx4 = r * 256 + tid;
        int row = idx4 >> 4, col = (idx4 & 15) * 4;
        *(float4*)(Qs + row * 64 + col) = *(const float4*)(Qb + (size_t)row * QLD + col);
    }

    float m[4], l[4], o[4][4];
#pragma unroll
    for (int u = 0; u < 4; u++) {
        m[u] = -1e30f; l[u] = 0.f;
#pragma unroll
        for (int w = 0; w < 4; w++) o[u][w] = 0.f;
    }

    for (int kv = 0; kv < S_; kv += 64) {
#pragma unroll
        for (int r = 0; r < 4; r++) {
            int idx4 = r * 256 + tid;
            int c = idx4 >> 4, i = (idx4 & 15) * 4;
            float4 k4 = *(const float4*)(Kb + (size_t)(kv + c) * QLD + i);
            float4 v4 = *(const float4*)(Vb + (size_t)(kv + c) * QLD + i);
            Ks[c * 65 + i + 0] = k4.x; Ks[c * 65 + i + 1] = k4.y;
            Ks[c * 65 + i + 2] = k4.z; Ks[c * 65 + i + 3] = k4.w;
            Vs[c * 65 + i + 0] = v4.x; Vs[c * 65 + i + 1] = v4.y;
            Vs[c * 65 + i + 2] = v4.z; Vs[c * 65 + i + 3] = v4.w;
        }
        __syncthreads();

        float acc[4][4] = {};
#pragma unroll 8
        for (int i = 0; i < 64; i++) {
            float a[4], b[4];
#pragma unroll
            for (int u = 0; u < 4; u++) a[u] = Qs[(ty * 4 + u) * 64 + i];
#pragma unroll
            for (int w = 0; w < 4; w++) b[w] = Ks[(tx * 4 + w) * 65 + i];
#pragma unroll
            for (int u = 0; u < 4; u++)
#pragma unroll
                for (int w = 0; w < 4; w++) acc[u][w] += a[u] * b[w];
        }

#pragma unroll
        for (int u = 0; u < 4; u++) {
            float rmax = fmaxf(fmaxf(acc[u][0], acc[u][1]), fmaxf(acc[u][2], acc[u][3]));
#pragma unroll
            for (int off = 8; off > 0; off >>= 1)
                rmax = fmaxf(rmax, __shfl_xor_sync(0xffffffffu, rmax, off));
            float mn = fmaxf(m[u], rmax);
            float corr = __expf(m[u] - mn);
            float ps = 0.f;
#pragma unroll
            for (int w = 0; w < 4; w++) {
                acc[u][w] = __expf(acc[u][w] - mn);
                ps += acc[u][w];
            }
#pragma unroll
            for (int off = 8; off > 0; off >>= 1)
                ps += __shfl_xor_sync(0xffffffffu, ps, off);
            l[u] = l[u] * corr + ps;
            m[u] = mn;
#pragma unroll
            for (int w = 0; w < 4; w++) o[u][w] *= corr;
        }
        __syncthreads();

#pragma unroll
        for (int u = 0; u < 4; u++)
#pragma unroll
            for (int w = 0; w < 4; w++)
                Ks[(ty * 4 + u) * 65 + tx * 4 + w] = acc[u][w];
        __syncthreads();

#pragma unroll 8
        for (int c = 0; c < 64; c++) {
            float a[4], b[4];
#pragma unroll
            for (int u = 0; u < 4; u++) a[u] = Ks[(ty * 4 + u) * 65 + c];
#pragma unroll
            for (int w = 0; w < 4; w++) b[w] = Vs[c * 65 + tx * 4 + w];
#pragma unroll
            for (int u = 0; u < 4; u++)
#pragma unroll
                for (int w = 0; w < 4; w++) o[u][w] += a[u] * b[w];
        }
        __syncthreads();
    }

#pragma unroll
    for (int u = 0; u < 4; u++) {
        float inv = 1.f / l[u];
        int s = q0 + ty * 4 + u;
#pragma unroll
        for (int w = 0; w < 4; w++) {
            size_t off = ((size_t)b_ * S_ + s) * D_ + h * HD_ + tx * 4 + w;
            bf16 hh, ll; split_bf16(o[u][w] * inv, hh, ll);
            Ohi[off] = hh; Olo[off] = ll;
        }
    }
}

// ---------------------------------------------------------------------------
// Launch
// ---------------------------------------------------------------------------
extern "C" void kernel_launch(void* const* d_in, const int* in_sizes, int n_in,
                              void* d_out, int out_size) {
    const float* x   = (const float*)d_in[0];
    const float* Wq  = (const float*)d_in[1];
    const float* bq  = (const float*)d_in[2];
    const float* Wk  = (const float*)d_in[3];
    const float* bk  = (const float*)d_in[4];
    const float* Wv  = (const float*)d_in[5];
    const float* bv  = (const float*)d_in[6];
    const float* Wp  = (const float*)d_in[7];
    const float* bp  = (const float*)d_in[8];
    const float* W1  = (const float*)d_in[9];
    const float* b1  = (const float*)d_in[10];
    const float* W2  = (const float*)d_in[11];
    const float* b2  = (const float*)d_in[12];
    const float* g1  = (const float*)d_in[13];
    const float* be1 = (const float*)d_in[14];
    const float* g2  = (const float*)d_in[15];
    const float* be2 = (const float*)d_in[16];
    float* out = (float*)d_out;

    bf16 *xn_hi, *xn_lo, *attn_hi, *attn_lo, *h_hi, *h_lo;
    bf16 *wqkv_hi, *wqkv_lo, *wp_hi, *wp_lo, *w1_hi, *w1_lo, *w2_hi, *w2_lo;
    float *qkv, *bqkv;
    cudaGetSymbolAddress((void**)&xn_hi, g_xn_hi);     cudaGetSymbolAddress((void**)&xn_lo, g_xn_lo);
    cudaGetSymbolAddress((void**)&attn_hi, g_attn_hi); cudaGetSymbolAddress((void**)&attn_lo, g_attn_lo);
    cudaGetSymbolAddress((void**)&h_hi, g_h_hi);       cudaGetSymbolAddress((void**)&h_lo, g_h_lo);
    cudaGetSymbolAddress((void**)&wqkv_hi, g_wqkv_hi); cudaGetSymbolAddress((void**)&wqkv_lo, g_wqkv_lo);
    cudaGetSymbolAddress((void**)&wp_hi, g_wp_hi);     cudaGetSymbolAddress((void**)&wp_lo, g_wp_lo);
    cudaGetSymbolAddress((void**)&w1_hi, g_w1_hi);     cudaGetSymbolAddress((void**)&w1_lo, g_w1_lo);
    cudaGetSymbolAddress((void**)&w2_hi, g_w2_hi);     cudaGetSymbolAddress((void**)&w2_lo, g_w2_lo);
    cudaGetSymbolAddress((void**)&qkv, g_qkv);
    cudaGetSymbolAddress((void**)&bqkv, g_bqkv);

    cudaFuncSetAttribute(flash_kernel, cudaFuncAttributeMaxDynamicSharedMemorySize,
                         FLASH_SMEM_FLOATS * (int)sizeof(float));

    dim3 tb(32, 8);
    // weight conversion (transposed + bf16 split); Q/K/V into one [1536,512]
    convw_qkv<<<dim3(D_ / 32, HD_ / 32, H_), tb>>>(Wq, wqkv_hi,             wqkv_lo);
    convw_qkv<<<dim3(D_ / 32, HD_ / 32, H_), tb>>>(Wk, wqkv_hi + D_ * D_,   wqkv_lo + D_ * D_);
    convw_qkv<<<dim3(D_ / 32, HD_ / 32, H_), tb>>>(Wv, wqkv_hi + 2 * D_ * D_, wqkv_lo + 2 * D_ * D_);
    convw_t<<<dim3(D_ / 32, D_ / 32), tb>>>(Wp, wp_hi, wp_lo, D_, D_);
    convw_t<<<dim3(D_ / 32, FF_ / 32), tb>>>(W1, w1_hi, w1_lo, D_, FF_);
    convw_t<<<dim3(FF_ / 32, D_ / 32), tb>>>(W2, w2_hi, w2_lo, FF_, D_);
    pack_bias<<<2, 256>>>(bq, bk, bv, bqkv);

    // LN1
    ln_kernel<<<T_, 256>>>(x, g1, be1, xn_hi, xn_lo);

    // fused QKV GEMM: [T,1536]
    mma_gemm<false, false, false><<<dim3(QKV_N / 128, T_ / 128), 256>>>(
        xn_hi, xn_lo, wqkv_hi, wqkv_lo, bqkv, nullptr, qkv, nullptr, nullptr, T_, QKV_N, D_);

    // flash attention -> attn bf16 pair
    flash_kernel<<<dim3(S_ / 64, B_ * H_), 256, FLASH_SMEM_FLOATS * sizeof(float)>>>(
        qkv, attn_hi, attn_lo);

    // proj + residual: out = x + attn @ Wp + bp
    mma_gemm<false, true, false><<<dim3(D_ / 128, T_ / 128), 256>>>(
        attn_hi, attn_lo, wp_hi, wp_lo, bp, x, out, nullptr, nullptr, T_, D_, D_);

    // LN2
    ln_kernel<<<T_, 256>>>(out, g2, be2, xn_hi, xn_lo);

    // MLP1 (ReLU) -> h bf16 pair
    mma_gemm<true, false, true><<<dim3(FF_ / 128, T_ / 128), 256>>>(
        xn_hi, xn_lo, w1_hi, w1_lo, b1, nullptr, nullptr, h_hi, h_lo, T_, FF_, D_);

    // MLP2 + residual (in place on out)
    mma_gemm<false, true, false><<<dim3(D_ / 128, T_ / 128), 256>>>(
        h_hi, h_lo, w2_hi, w2_lo, b2, out, out, nullptr, nullptr, T_, D_, FF_);
}

// round 5
// speedup vs baseline: 2.6318x; 1.8033x over previous
#include <cuda_runtime.h>
#include <cuda_bf16.h>
#include <cstdint>

// Problem constants
#define B_  2
#define S_  2048
#define D_  512
#define H_  8
#define HD_ 64
#define T_  (B_*S_)      // 4096 tokens
#define FF_ (4*D_)       // 2048
#define QKV_N (3*D_)     // 1536

typedef __nv_bfloat16 bf16;

// ---------------------------------------------------------------------------
// Scratch (device globals; no allocation allowed)
// ---------------------------------------------------------------------------
__device__ bf16 g_xn_hi[T_*D_], g_xn_lo[T_*D_];             // LN out
__device__ float g_qkv[(size_t)T_*QKV_N];                   // fused QKV fp32 [T,1536]
__device__ bf16 g_attn_hi[T_*D_], g_attn_lo[T_*D_];         // attention out [B,S,D]
__device__ bf16 g_h_hi[(size_t)T_*FF_], g_h_lo[(size_t)T_*FF_]; // MLP hidden
__device__ float g_bqkv[QKV_N];
// transposed+split weights: layout [N, K] bf16
__device__ bf16 g_wqkv_hi[QKV_N*D_], g_wqkv_lo[QKV_N*D_];
__device__ bf16 g_wp_hi[D_*D_], g_wp_lo[D_*D_];
__device__ bf16 g_w1_hi[D_*FF_], g_w1_lo[D_*FF_];
__device__ bf16 g_w2_hi[D_*FF_], g_w2_lo[D_*FF_];

// ---------------------------------------------------------------------------
// helpers
// ---------------------------------------------------------------------------
__device__ __forceinline__ uint32_t smem_to_u32(const void* p) {
    uint32_t a;
    asm("{ .reg .u64 tmp; cvta.to.shared.u64 tmp, %1; cvt.u32.u64 %0, tmp; }"
        : "=r"(a) : "l"(p));
    return a;
}
__device__ __forceinline__ void ldsm_x4(uint32_t* r, uint32_t addr) {
    asm volatile("ldmatrix.sync.aligned.m8n8.x4.shared.b16 {%0,%1,%2,%3}, [%4];"
        : "=r"(r[0]), "=r"(r[1]), "=r"(r[2]), "=r"(r[3]) : "r"(addr));
}
__device__ __forceinline__ void ldsm_x4_t(uint32_t* r, uint32_t addr) {
    asm volatile("ldmatrix.sync.aligned.m8n8.x4.trans.shared.b16 {%0,%1,%2,%3}, [%4];"
        : "=r"(r[0]), "=r"(r[1]), "=r"(r[2]), "=r"(r[3]) : "r"(addr));
}
__device__ __forceinline__ void mma16816(float* c, const uint32_t* a, const uint32_t* b) {
    asm volatile("mma.sync.aligned.m16n8k16.row.col.f32.bf16.bf16.f32 "
        "{%0,%1,%2,%3}, {%4,%5,%6,%7}, {%8,%9}, {%0,%1,%2,%3};"
        : "+f"(c[0]), "+f"(c[1]), "+f"(c[2]), "+f"(c[3])
        : "r"(a[0]), "r"(a[1]), "r"(a[2]), "r"(a[3]), "r"(b[0]), "r"(b[1]));
}
__device__ __forceinline__ void split_bf16(float v, bf16& h, bf16& l) {
    h = __float2bfloat16(v);
    l = __float2bfloat16(v - __bfloat162float(h));
}
__device__ __forceinline__ uint32_t pack_bf2(float a, float b) {
    __nv_bfloat162 p;
    p.x = __float2bfloat16(a);
    p.y = __float2bfloat16(b);
    return *(uint32_t*)&p;
}
// swizzled byte offset within a 128row x 64B tile (rows of 4 x 16B groups)
__device__ __forceinline__ uint32_t sw_off(int row, int g) {
    return (uint32_t)(((row << 2) | (g ^ ((row >> 1) & 3))) << 4);
}

// ---------------------------------------------------------------------------
// Weight conversion kernels
// ---------------------------------------------------------------------------
__global__ void convw_t(const float* __restrict__ W, bf16* __restrict__ hi,
                        bf16* __restrict__ lo, int K, int N) {
    __shared__ float t[32][33];
    int kb = blockIdx.x * 32, nb = blockIdx.y * 32;
    int tx = threadIdx.x, ty = threadIdx.y;     // 32 x 8
#pragma unroll
    for (int i = 0; i < 32; i += 8) t[ty + i][tx] = W[(size_t)(kb + ty + i) * N + nb + tx];
    __syncthreads();
#pragma unroll
    for (int i = 0; i < 32; i += 8) {
        float v = t[tx][ty + i];
        size_t o = (size_t)(nb + ty + i) * K + kb + tx;
        bf16 h, l; split_bf16(v, h, l);
        hi[o] = h; lo[o] = l;
    }
}
// QKV weights [H, D, HD] -> [N=H*HD, K=D]
__global__ void convw_qkv(const float* __restrict__ W, bf16* __restrict__ hi,
                          bf16* __restrict__ lo) {
    __shared__ float t[32][33];
    int h = blockIdx.z;
    int db = blockIdx.x * 32, eb = blockIdx.y * 32;
    const float* base = W + (size_t)h * D_ * HD_;
    int tx = threadIdx.x, ty = threadIdx.y;
#pragma unroll
    for (int i = 0; i < 32; i += 8) t[ty + i][tx] = base[(size_t)(db + ty + i) * HD_ + eb + tx];
    __syncthreads();
#pragma unroll
    for (int i = 0; i < 32; i += 8) {
        float v = t[tx][ty + i];
        int n = h * HD_ + eb + ty + i, k = db + tx;
        bf16 hh, ll; split_bf16(v, hh, ll);
        hi[(size_t)n * D_ + k] = hh; lo[(size_t)n * D_ + k] = ll;
    }
}
__global__ void pack_bias(const float* __restrict__ bq, const float* __restrict__ bk,
                          const float* __restrict__ bv, float* __restrict__ o) {
    int t = blockIdx.x * 256 + threadIdx.x;
    if (t < D_) { o[t] = bq[t]; o[t + D_] = bk[t]; o[t + 2 * D_] = bv[t]; }
}

// ---------------------------------------------------------------------------
// LayerNorm -> bf16 hi/lo pair. One block per row, 256 threads.
// ---------------------------------------------------------------------------
__global__ void ln_kernel(const float* __restrict__ x, const float* __restrict__ g,
                          const float* __restrict__ be, bf16* __restrict__ hi,
                          bf16* __restrict__ lo) {
    int row = blockIdx.x;
    int t = threadIdx.x;
    const float* xr = x + (size_t)row * D_;
    float v0 = xr[t], v1 = xr[t + 256];
    float s = v0 + v1, ss = v0 * v0 + v1 * v1;
#pragma unroll
    for (int o = 16; o > 0; o >>= 1) {
        s  += __shfl_xor_sync(0xffffffffu, s, o);
        ss += __shfl_xor_sync(0xffffffffu, ss, o);
    }
    __shared__ float rs[8], rss[8];
    if ((t & 31) == 0) { rs[t >> 5] = s; rss[t >> 5] = ss; }
    __syncthreads();
    s = 0.f; ss = 0.f;
#pragma unroll
    for (int i = 0; i < 8; i++) { s += rs[i]; ss += rss[i]; }
    float mean = s * (1.f / (float)D_);
    float var  = ss * (1.f / (float)D_) - mean * mean;
    float r = rsqrtf(var + 1e-5f);
    float y0 = (v0 - mean) * r * g[t] + be[t];
    float y1 = (v1 - mean) * r * g[t + 256] + be[t + 256];
    bf16 h, l;
    split_bf16(y0, h, l); hi[(size_t)row * D_ + t] = h;       lo[(size_t)row * D_ + t] = l;
    split_bf16(y1, h, l); hi[(size_t)row * D_ + t + 256] = h; lo[(size_t)row * D_ + t + 256] = l;
}

// ---------------------------------------------------------------------------
// mma.sync GEMM with bf16x3 compensation (unchanged from R3 passing version)
// ---------------------------------------------------------------------------
#define SMT_AHI 0
#define SMT_ALO 8192
#define SMT_BHI 16384
#define SMT_BLO 24576

template <bool RELU, bool RES, bool OUTPAIR>
__global__ void __launch_bounds__(256, 2) mma_gemm(
    const bf16* __restrict__ Ahi, const bf16* __restrict__ Alo,
    const bf16* __restrict__ Bhi, const bf16* __restrict__ Blo,
    const float* __restrict__ bias, const float* __restrict__ res,
    float* __restrict__ Cf, bf16* __restrict__ Chi, bf16* __restrict__ Clo,
    int M, int N, int K) {
    __shared__ __align__(128) char smem_buf[32768];
    uint32_t sb = smem_to_u32(smem_buf);
    int tid = threadIdx.x, lane = tid & 31, wid = tid >> 5;
    int wm = wid >> 2, wn = wid & 3;
    int m0 = blockIdx.y * 128, n0 = blockIdx.x * 128;

    float acc[4][4][4];
#pragma unroll
    for (int a = 0; a < 4; a++)
#pragma unroll
        for (int b = 0; b < 4; b++)
#pragma unroll
            for (int cc = 0; cc < 4; cc++) acc[a][b][cc] = 0.f;

    int ldrow = tid >> 2, ldg_ = tid & 3;
    int nchunk = K >> 5;
    for (int c = 0; c < nchunk; c++) {
        int k0 = c << 5;
#pragma unroll
        for (int it = 0; it < 2; it++) {
            int row = ldrow + it * 64;
            uint32_t off = sw_off(row, ldg_);
            size_t ao = (size_t)(m0 + row) * K + k0 + ldg_ * 8;
            size_t bo = (size_t)(n0 + row) * K + k0 + ldg_ * 8;
            *(float4*)(smem_buf + SMT_AHI + off) = *(const float4*)(Ahi + ao);
            *(float4*)(smem_buf + SMT_ALO + off) = *(const float4*)(Alo + ao);
            *(float4*)(smem_buf + SMT_BHI + off) = *(const float4*)(Bhi + bo);
            *(float4*)(smem_buf + SMT_BLO + off) = *(const float4*)(Blo + bo);
        }
        __syncthreads();
#pragma unroll
        for (int ks = 0; ks < 2; ks++) {
            int kg = ks * 2;
            uint32_t bh[4][2], bl[4][2];
#pragma unroll
            for (int ntp = 0; ntp < 2; ntp++) {
                int nrow = wn * 32 + ntp * 16 + (lane & 7) + ((lane >> 4) & 1) * 8;
                int bg = kg + ((lane >> 3) & 1);
                uint32_t off = sw_off(nrow, bg);
                uint32_t t4[4];
                ldsm_x4(t4, sb + SMT_BHI + off);
                bh[ntp * 2][0] = t4[0]; bh[ntp * 2][1] = t4[1];
                bh[ntp * 2 + 1][0] = t4[2]; bh[ntp * 2 + 1][1] = t4[3];
                ldsm_x4(t4, sb + SMT_BLO + off);
                bl[ntp * 2][0] = t4[0]; bl[ntp * 2][1] = t4[1];
                bl[ntp * 2 + 1][0] = t4[2]; bl[ntp * 2 + 1][1] = t4[3];
            }
#pragma unroll
            for (int mt = 0; mt < 4; mt++) {
                int arow = wm * 64 + mt * 16 + (lane & 7) + ((lane >> 3) & 1) * 8;
                int ag = kg + (lane >> 4);
                uint32_t off = sw_off(arow, ag);
                uint32_t ah[4], al[4];
                ldsm_x4(ah, sb + SMT_AHI + off);
                ldsm_x4(al, sb + SMT_ALO + off);
#pragma unroll
                for (int nt = 0; nt < 4; nt++) {
                    mma16816(acc[mt][nt], ah, bh[nt]);
                    mma16816(acc[mt][nt], ah, bl[nt]);
                    mma16816(acc[mt][nt], al, bh[nt]);
                }
            }
        }
        __syncthreads();
    }

#pragma unroll
    for (int mt = 0; mt < 4; mt++) {
#pragma unroll
        for (int nt = 0; nt < 4; nt++) {
            int r0 = m0 + wm * 64 + mt * 16 + (lane >> 2);
            int col = n0 + wn * 32 + nt * 8 + (lane & 3) * 2;
            float b0 = __ldg(bias + col), b1 = __ldg(bias + col + 1);
            float v00 = acc[mt][nt][0] + b0, v01 = acc[mt][nt][1] + b1;
            float v10 = acc[mt][nt][2] + b0, v11 = acc[mt][nt][3] + b1;
            if (RELU) {
                v00 = fmaxf(v00, 0.f); v01 = fmaxf(v01, 0.f);
                v10 = fmaxf(v10, 0.f); v11 = fmaxf(v11, 0.f);
            }
            if (OUTPAIR) {
                bf16 h, l;
                __nv_bfloat162 ph, pl;
                split_bf16(v00, h, l); ph.x = h; pl.x = l;
                split_bf16(v01, h, l); ph.y = h; pl.y = l;
                *(__nv_bfloat162*)(Chi + (size_t)r0 * N + col) = ph;
                *(__nv_bfloat162*)(Clo + (size_t)r0 * N + col) = pl;
                split_bf16(v10, h, l); ph.x = h; pl.x = l;
                split_bf16(v11, h, l); ph.y = h; pl.y = l;
                *(__nv_bfloat162*)(Chi + (size_t)(r0 + 8) * N + col) = ph;
                *(__nv_bfloat162*)(Clo + (size_t)(r0 + 8) * N + col) = pl;
            } else {
                if (RES) {
                    float2 ra = *(const float2*)(res + (size_t)r0 * N + col);
                    float2 rb = *(const float2*)(res + (size_t)(r0 + 8) * N + col);
                    v00 += ra.x; v01 += ra.y; v10 += rb.x; v11 += rb.y;
                }
                float2 o0 = {v00, v01}, o1 = {v10, v11};
                *(float2*)(Cf + (size_t)r0 * N + col) = o0;
                *(float2*)(Cf + (size_t)(r0 + 8) * N + col) = o1;
            }
        }
    }
}

// ---------------------------------------------------------------------------
// Flash attention on tensor cores with bf16x3 compensation.
// Q-tile 64 rows (4 warps x m16), KV-tile 64, HD=64. 128 threads.
// Q/K/V read from fused fp32 qkv buffer [T,1536]; split to bf16 hi/lo in smem.
// P stays in registers: S C-fragments map directly to PV A-fragments.
// smem: K/V tiles [64][72] bf16 hi/lo (stride 144B); Q staged transiently.
// ---------------------------------------------------------------------------
#define QLD QKV_N
#define FPAD 72                         // bf16 elems per row (144 bytes)
#define FK_HI 0
#define FK_LO (64*FPAD*2)
#define FV_HI (2*64*FPAD*2)
#define FV_LO (3*64*FPAD*2)
#define FLASH_SMEM (4*64*FPAD*2)        // 36864 bytes

__global__ void __launch_bounds__(128) flash_mma_kernel(
    const float* __restrict__ QKV, bf16* __restrict__ Ohi, bf16* __restrict__ Olo) {
    extern __shared__ __align__(16) char fsm[];
    uint32_t sb = smem_to_u32(fsm);
    int tid = threadIdx.x, lane = tid & 31, wid = tid >> 5;
    int bh = blockIdx.y;
    int b_ = bh >> 3, h = bh & 7;
    int q0 = blockIdx.x * 64;

    const float* Qb = QKV + ((size_t)b_ * S_ + q0) * QLD + h * HD_;
    const float* Kb = QKV + (size_t)b_ * S_ * QLD + D_ + h * HD_;
    const float* Vb = QKV + (size_t)b_ * S_ * QLD + 2 * D_ + h * HD_;

    // --- stage Q (64x64 fp32 -> hi/lo bf16 in smem at FK_HI/FK_LO) ---
#pragma unroll
    for (int it = 0; it < 8; it++) {
        int idx = it * 128 + tid;          // 0..1023
        int row = idx >> 4, fg = idx & 15; // fg: float4 group (4 cols)
        float4 qv = *(const float4*)(Qb + (size_t)row * QLD + fg * 4);
        bf16 hx, lx, hy, ly, hz, lz, hw, lw;
        split_bf16(qv.x, hx, lx); split_bf16(qv.y, hy, ly);
        split_bf16(qv.z, hz, lz); split_bf16(qv.w, hw, lw);
        uint32_t off = (uint32_t)(row * (FPAD * 2) + fg * 8);
        __nv_bfloat162 p0, p1;
        p0.x = hx; p0.y = hy; p1.x = hz; p1.y = hw;
        *(uint2*)(fsm + FK_HI + off) = make_uint2(*(uint32_t*)&p0, *(uint32_t*)&p1);
        p0.x = lx; p0.y = ly; p1.x = lz; p1.y = lw;
        *(uint2*)(fsm + FK_LO + off) = make_uint2(*(uint32_t*)&p0, *(uint32_t*)&p1);
    }
    __syncthreads();

    // extract Q A-fragments (held in regs whole kernel); warp w -> rows 16w..16w+15
    uint32_t qh[4][4], ql[4][4];
    {
        int arow = wid * 16 + (lane & 7) + ((lane >> 3) & 1) * 8;
#pragma unroll
        for (int ks = 0; ks < 4; ks++) {
            uint32_t off = (uint32_t)(arow * (FPAD * 2) + (ks * 2 + (lane >> 4)) * 16);
            ldsm_x4(qh[ks], sb + FK_HI + off);
            ldsm_x4(ql[ks], sb + FK_LO + off);
        }
    }
    __syncthreads();   // Q region about to be overwritten by K tiles

    // --- online softmax state (2 rows per thread: r and r+8) ---
    float m0 = -1e30f, m1 = -1e30f, l0 = 0.f, l1 = 0.f;
    float oacc[8][4];
#pragma unroll
    for (int i = 0; i < 8; i++)
#pragma unroll
        for (int j = 0; j < 4; j++) oacc[i][j] = 0.f;

    for (int kv = 0; kv < S_; kv += 64) {
        // load K,V tiles (fp32 -> hi/lo bf16)
#pragma unroll
        for (int it = 0; it < 8; it++) {
            int idx = it * 128 + tid;
            int row = idx >> 4, fg = idx & 15;
            uint32_t off = (uint32_t)(row * (FPAD * 2) + fg * 8);
            float4 kvl = *(const float4*)(Kb + (size_t)(kv + row) * QLD + fg * 4);
            bf16 hx, lx, hy, ly, hz, lz, hw, lw;
            split_bf16(kvl.x, hx, lx); split_bf16(kvl.y, hy, ly);
            split_bf16(kvl.z, hz, lz); split_bf16(kvl.w, hw, lw);
            __nv_bfloat162 p0, p1;
            p0.x = hx; p0.y = hy; p1.x = hz; p1.y = hw;
            *(uint2*)(fsm + FK_HI + off) = make_uint2(*(uint32_t*)&p0, *(uint32_t*)&p1);
            p0.x = lx; p0.y = ly; p1.x = lz; p1.y = lw;
            *(uint2*)(fsm + FK_LO + off) = make_uint2(*(uint32_t*)&p0, *(uint32_t*)&p1);
            float4 vvl = *(const float4*)(Vb + (size_t)(kv + row) * QLD + fg * 4);
            split_bf16(vvl.x, hx, lx); split_bf16(vvl.y, hy, ly);
            split_bf16(vvl.z, hz, lz); split_bf16(vvl.w, hw, lw);
            p0.x = hx; p0.y = hy; p1.x = hz; p1.y = hw;
            *(uint2*)(fsm + FV_HI + off) = make_uint2(*(uint32_t*)&p0, *(uint32_t*)&p1);
            p0.x = lx; p0.y = ly; p1.x = lz; p1.y = lw;
            *(uint2*)(fsm + FV_LO + off) = make_uint2(*(uint32_t*)&p0, *(uint32_t*)&p1);
        }
        __syncthreads();

        // --- S = Q K^T (64 kv cols = 8 n-tiles), bf16x3 ---
        float sacc[8][4];
#pragma unroll
        for (int i = 0; i < 8; i++)
#pragma unroll
            for (int j = 0; j < 4; j++) sacc[i][j] = 0.f;

#pragma unroll
        for (int ng = 0; ng < 4; ng++) {     // 16 kv rows per group
            int nrow = ng * 16 + (lane & 7) + ((lane >> 4) & 1) * 8;
#pragma unroll
            for (int ks = 0; ks < 4; ks++) {
                int bg = ks * 2 + ((lane >> 3) & 1);
                uint32_t off = (uint32_t)(nrow * (FPAD * 2) + bg * 16);
                uint32_t th[4], tl[4];
                ldsm_x4(th, sb + FK_HI + off);
                ldsm_x4(tl, sb + FK_LO + off);
                uint32_t bh0[2] = {th[0], th[1]}, bh1[2] = {th[2], th[3]};
                uint32_t bl0[2] = {tl[0], tl[1]}, bl1[2] = {tl[2], tl[3]};
                mma16816(sacc[ng * 2],     qh[ks], bh0);
                mma16816(sacc[ng * 2],     qh[ks], bl0);
                mma16816(sacc[ng * 2],     ql[ks], bh0);
                mma16816(sacc[ng * 2 + 1], qh[ks], bh1);
                mma16816(sacc[ng * 2 + 1], qh[ks], bl1);
                mma16816(sacc[ng * 2 + 1], ql[ks], bh1);
            }
        }

        // --- online softmax on fragments ---
        float rmax0 = -1e30f, rmax1 = -1e30f;
#pragma unroll
        for (int nt = 0; nt < 8; nt++) {
            rmax0 = fmaxf(rmax0, fmaxf(sacc[nt][0], sacc[nt][1]));
            rmax1 = fmaxf(rmax1, fmaxf(sacc[nt][2], sacc[nt][3]));
        }
        rmax0 = fmaxf(rmax0, __shfl_xor_sync(0xffffffffu, rmax0, 1));
        rmax0 = fmaxf(rmax0, __shfl_xor_sync(0xffffffffu, rmax0, 2));
        rmax1 = fmaxf(rmax1, __shfl_xor_sync(0xffffffffu, rmax1, 1));
        rmax1 = fmaxf(rmax1, __shfl_xor_sync(0xffffffffu, rmax1, 2));
        float mn0 = fmaxf(m0, rmax0), mn1 = fmaxf(m1, rmax1);
        float corr0 = __expf(m0 - mn0), corr1 = __expf(m1 - mn1);
        float ps0 = 0.f, ps1 = 0.f;
#pragma unroll
        for (int nt = 0; nt < 8; nt++) {
            sacc[nt][0] = __expf(sacc[nt][0] - mn0);
            sacc[nt][1] = __expf(sacc[nt][1] - mn0);
            sacc[nt][2] = __expf(sacc[nt][2] - mn1);
            sacc[nt][3] = __expf(sacc[nt][3] - mn1);
            ps0 += sacc[nt][0] + sacc[nt][1];
            ps1 += sacc[nt][2] + sacc[nt][3];
        }
        ps0 += __shfl_xor_sync(0xffffffffu, ps0, 1);
        ps0 += __shfl_xor_sync(0xffffffffu, ps0, 2);
        ps1 += __shfl_xor_sync(0xffffffffu, ps1, 1);
        ps1 += __shfl_xor_sync(0xffffffffu, ps1, 2);
        l0 = l0 * corr0 + ps0; l1 = l1 * corr1 + ps1;
        m0 = mn0; m1 = mn1;
#pragma unroll
        for (int i = 0; i < 8; i++) {
            oacc[i][0] *= corr0; oacc[i][1] *= corr0;
            oacc[i][2] *= corr1; oacc[i][3] *= corr1;
        }

        // --- O += P V : P fragments built from sacc (no smem round-trip) ---
#pragma unroll
        for (int kc = 0; kc < 4; kc++) {   // kv 16-chunks
            float* pa = sacc[kc * 2];      // k 0-7 of chunk
            float* pb = sacc[kc * 2 + 1];  // k 8-15
            uint32_t phi[4], plo[4];
            phi[0] = pack_bf2(pa[0], pa[1]);
            phi[1] = pack_bf2(pa[2], pa[3]);
            phi[2] = pack_bf2(pb[0], pb[1]);
            phi[3] = pack_bf2(pb[2], pb[3]);
            {
                __nv_bfloat162 h0 = *(__nv_bfloat162*)&phi[0];
                __nv_bfloat162 h1 = *(__nv_bfloat162*)&phi[1];
                __nv_bfloat162 h2 = *(__nv_bfloat162*)&phi[2];
                __nv_bfloat162 h3 = *(__nv_bfloat162*)&phi[3];
                plo[0] = pack_bf2(pa[0] - __bfloat162float(h0.x), pa[1] - __bfloat162float(h0.y));
                plo[1] = pack_bf2(pa[2] - __bfloat162float(h1.x), pa[3] - __bfloat162float(h1.y));
                plo[2] = pack_bf2(pb[0] - __bfloat162float(h2.x), pb[1] - __bfloat162float(h2.y));
                plo[3] = pack_bf2(pb[2] - __bfloat162float(h3.x), pb[3] - __bfloat162float(h3.y));
            }
#pragma unroll
            for (int hg = 0; hg < 4; hg++) {    // hd 16-col groups
                int vrow = kc * 16 + ((lane >> 3) & 1) * 8 + (lane & 7);
                int vcol = hg * 16 + ((lane >> 4) & 1) * 8;
                uint32_t off = (uint32_t)(vrow * (FPAD * 2) + vcol * 2);
                uint32_t th[4], tl[4];
                ldsm_x4_t(th, sb + FV_HI + off);
                ldsm_x4_t(tl, sb + FV_LO + off);
                uint32_t bh0[2] = {th[0], th[1]}, bh1[2] = {th[2], th[3]};
                uint32_t bl0[2] = {tl[0], tl[1]}, bl1[2] = {tl[2], tl[3]};
                mma16816(oacc[hg * 2],     phi, bh0);
                mma16816(oacc[hg * 2],     phi, bl0);
                mma16816(oacc[hg * 2],     plo, bh0);
                mma16816(oacc[hg * 2 + 1], phi, bh1);
                mma16816(oacc[hg * 2 + 1], phi, bl1);
                mma16816(oacc[hg * 2 + 1], plo, bh1);
            }
        }
        __syncthreads();   // done reading K/V before next tile overwrites
    }

    // --- write O / l as bf16 hi/lo pairs ---
    float inv0 = 1.f / l0, inv1 = 1.f / l1;
    int r0 = q0 + wid * 16 + (lane >> 2);
#pragma unroll
    for (int nt = 0; nt < 8; nt++) {
        int col = h * HD_ + nt * 8 + (lane & 3) * 2;
        float v00 = oacc[nt][0] * inv0, v01 = oacc[nt][1] * inv0;
        float v10 = oacc[nt][2] * inv1, v11 = oacc[nt][3] * inv1;
        bf16 hh, ll;
        __nv_bfloat162 ph, pl;
        split_bf16(v00, hh, ll); ph.x = hh; pl.x = ll;
        split_bf16(v01, hh, ll); ph.y = hh; pl.y = ll;
        *(__nv_bfloat162*)(Ohi + ((size_t)b_ * S_ + r0) * D_ + col) = ph;
        *(__nv_bfloat162*)(Olo + ((size_t)b_ * S_ + r0) * D_ + col) = pl;
        split_bf16(v10, hh, ll); ph.x = hh; pl.x = ll;
        split_bf16(v11, hh, ll); ph.y = hh; pl.y = ll;
        *(__nv_bfloat162*)(Ohi + ((size_t)b_ * S_ + r0 + 8) * D_ + col) = ph;
        *(__nv_bfloat162*)(Olo + ((size_t)b_ * S_ + r0 + 8) * D_ + col) = pl;
    }
}

// ---------------------------------------------------------------------------
// Launch
// ---------------------------------------------------------------------------
extern "C" void kernel_launch(void* const* d_in, const int* in_sizes, int n_in,
                              void* d_out, int out_size) {
    const float* x   = (const float*)d_in[0];
    const float* Wq  = (const float*)d_in[1];
    const float* bq  = (const float*)d_in[2];
    const float* Wk  = (const float*)d_in[3];
    const float* bk  = (const float*)d_in[4];
    const float* Wv  = (const float*)d_in[5];
    const float* bv  = (const float*)d_in[6];
    const float* Wp  = (const float*)d_in[7];
    const float* bp  = (const float*)d_in[8];
    const float* W1  = (const float*)d_in[9];
    const float* b1  = (const float*)d_in[10];
    const float* W2  = (const float*)d_in[11];
    const float* b2  = (const float*)d_in[12];
    const float* g1  = (const float*)d_in[13];
    const float* be1 = (const float*)d_in[14];
    const float* g2  = (const float*)d_in[15];
    const float* be2 = (const float*)d_in[16];
    float* out = (float*)d_out;

    bf16 *xn_hi, *xn_lo, *attn_hi, *attn_lo, *h_hi, *h_lo;
    bf16 *wqkv_hi, *wqkv_lo, *wp_hi, *wp_lo, *w1_hi, *w1_lo, *w2_hi, *w2_lo;
    float *qkv, *bqkv;
    cudaGetSymbolAddress((void**)&xn_hi, g_xn_hi);     cudaGetSymbolAddress((void**)&xn_lo, g_xn_lo);
    cudaGetSymbolAddress((void**)&attn_hi, g_attn_hi); cudaGetSymbolAddress((void**)&attn_lo, g_attn_lo);
    cudaGetSymbolAddress((void**)&h_hi, g_h_hi);       cudaGetSymbolAddress((void**)&h_lo, g_h_lo);
    cudaGetSymbolAddress((void**)&wqkv_hi, g_wqkv_hi); cudaGetSymbolAddress((void**)&wqkv_lo, g_wqkv_lo);
    cudaGetSymbolAddress((void**)&wp_hi, g_wp_hi);     cudaGetSymbolAddress((void**)&wp_lo, g_wp_lo);
    cudaGetSymbolAddress((void**)&w1_hi, g_w1_hi);     cudaGetSymbolAddress((void**)&w1_lo, g_w1_lo);
    cudaGetSymbolAddress((void**)&w2_hi, g_w2_hi);     cudaGetSymbolAddress((void**)&w2_lo, g_w2_lo);
    cudaGetSymbolAddress((void**)&qkv, g_qkv);
    cudaGetSymbolAddress((void**)&bqkv, g_bqkv);

    cudaFuncSetAttribute(flash_mma_kernel, cudaFuncAttributeMaxDynamicSharedMemorySize,
                         FLASH_SMEM);

    dim3 tb(32, 8);
    convw_qkv<<<dim3(D_ / 32, HD_ / 32, H_), tb>>>(Wq, wqkv_hi,               wqkv_lo);
    convw_qkv<<<dim3(D_ / 32, HD_ / 32, H_), tb>>>(Wk, wqkv_hi + D_ * D_,     wqkv_lo + D_ * D_);
    convw_qkv<<<dim3(D_ / 32, HD_ / 32, H_), tb>>>(Wv, wqkv_hi + 2 * D_ * D_, wqkv_lo + 2 * D_ * D_);
    convw_t<<<dim3(D_ / 32, D_ / 32), tb>>>(Wp, wp_hi, wp_lo, D_, D_);
    convw_t<<<dim3(D_ / 32, FF_ / 32), tb>>>(W1, w1_hi, w1_lo, D_, FF_);
    convw_t<<<dim3(FF_ / 32, D_ / 32), tb>>>(W2, w2_hi, w2_lo, FF_, D_);
    pack_bias<<<2, 256>>>(bq, bk, bv, bqkv);

    // LN1
    ln_kernel<<<T_, 256>>>(x, g1, be1, xn_hi, xn_lo);

    // fused QKV GEMM: [T,1536]
    mma_gemm<false, false, false><<<dim3(QKV_N / 128, T_ / 128), 256>>>(
        xn_hi, xn_lo, wqkv_hi, wqkv_lo, bqkv, nullptr, qkv, nullptr, nullptr, T_, QKV_N, D_);

    // flash attention (tensor cores) -> attn bf16 pair
    flash_mma_kernel<<<dim3(S_ / 64, B_ * H_), 128, FLASH_SMEM>>>(qkv, attn_hi, attn_lo);

    // proj + residual: out = x + attn @ Wp + bp
    mma_gemm<false, true, false><<<dim3(D_ / 128, T_ / 128), 256>>>(
        attn_hi, attn_lo, wp_hi, wp_lo, bp, x, out, nullptr, nullptr, T_, D_, D_);

    // LN2
    ln_kernel<<<T_, 256>>>(out, g2, be2, xn_hi, xn_lo);

    // MLP1 (ReLU) -> h bf16 pair
    mma_gemm<true, false, true><<<dim3(FF_ / 128, T_ / 128), 256>>>(
        xn_hi, xn_lo, w1_hi, w1_lo, b1, nullptr, nullptr, h_hi, h_lo, T_, FF_, D_);

    // MLP2 + residual (in place on out)
    mma_gemm<false, true, false><<<dim3(D_ / 128, T_ / 128), 256>>>(
        h_hi, h_lo, w2_hi, w2_lo, b2, out, out, nullptr, nullptr, T_, D_, FF_);
}

// round 6
// speedup vs baseline: 2.9170x; 1.1084x over previous
#include <cuda_runtime.h>
#include <cuda_bf16.h>
#include <cstdint>

// Problem constants
#define B_  2
#define S_  2048
#define D_  512
#define H_  8
#define HD_ 64
#define T_  (B_*S_)      // 4096 tokens
#define FF_ (4*D_)       // 2048
#define QKV_N (3*D_)     // 1536

typedef __nv_bfloat16 bf16;

// ---------------------------------------------------------------------------
// Scratch (device globals; no allocation allowed)
// ---------------------------------------------------------------------------
__device__ bf16 g_xn_hi[T_*D_], g_xn_lo[T_*D_];             // LN out
// q/k/v bf16 pairs, head-major: [which][b][h][s][hd]
__device__ bf16 g_qkvb_hi[3*T_*D_], g_qkvb_lo[3*T_*D_];
__device__ bf16 g_attn_hi[T_*D_], g_attn_lo[T_*D_];         // attention out [B,S,D]
__device__ bf16 g_h_hi[(size_t)T_*FF_], g_h_lo[(size_t)T_*FF_]; // MLP hidden
__device__ float g_bqkv[QKV_N];
// transposed+split weights: layout [N, K] bf16
__device__ bf16 g_wqkv_hi[QKV_N*D_], g_wqkv_lo[QKV_N*D_];
__device__ bf16 g_wp_hi[D_*D_], g_wp_lo[D_*D_];
__device__ bf16 g_w1_hi[D_*FF_], g_w1_lo[D_*FF_];
__device__ bf16 g_w2_hi[D_*FF_], g_w2_lo[D_*FF_];

// ---------------------------------------------------------------------------
// helpers
// ---------------------------------------------------------------------------
__device__ __forceinline__ uint32_t smem_to_u32(const void* p) {
    uint32_t a;
    asm("{ .reg .u64 tmp; cvta.to.shared.u64 tmp, %1; cvt.u32.u64 %0, tmp; }"
        : "=r"(a) : "l"(p));
    return a;
}
__device__ __forceinline__ void cp16(uint32_t smem, const void* g) {
    asm volatile("cp.async.ca.shared.global [%0], [%1], 16;" :: "r"(smem), "l"(g));
}
#define CP_COMMIT() asm volatile("cp.async.commit_group;" ::: "memory")
#define CP_WAIT1()  asm volatile("cp.async.wait_group 1;" ::: "memory")
#define CP_WAIT0()  asm volatile("cp.async.wait_group 0;" ::: "memory")

__device__ __forceinline__ void ldsm_x4(uint32_t* r, uint32_t addr) {
    asm volatile("ldmatrix.sync.aligned.m8n8.x4.shared.b16 {%0,%1,%2,%3}, [%4];"
        : "=r"(r[0]), "=r"(r[1]), "=r"(r[2]), "=r"(r[3]) : "r"(addr));
}
__device__ __forceinline__ void ldsm_x4_t(uint32_t* r, uint32_t addr) {
    asm volatile("ldmatrix.sync.aligned.m8n8.x4.trans.shared.b16 {%0,%1,%2,%3}, [%4];"
        : "=r"(r[0]), "=r"(r[1]), "=r"(r[2]), "=r"(r[3]) : "r"(addr));
}
__device__ __forceinline__ void mma16816(float* c, const uint32_t* a, const uint32_t* b) {
    asm volatile("mma.sync.aligned.m16n8k16.row.col.f32.bf16.bf16.f32 "
        "{%0,%1,%2,%3}, {%4,%5,%6,%7}, {%8,%9}, {%0,%1,%2,%3};"
        : "+f"(c[0]), "+f"(c[1]), "+f"(c[2]), "+f"(c[3])
        : "r"(a[0]), "r"(a[1]), "r"(a[2]), "r"(a[3]), "r"(b[0]), "r"(b[1]));
}
__device__ __forceinline__ void split_bf16(float v, bf16& h, bf16& l) {
    h = __float2bfloat16(v);
    l = __float2bfloat16(v - __bfloat162float(h));
}
__device__ __forceinline__ uint32_t pack_bf2(float a, float b) {
    __nv_bfloat162 p;
    p.x = __float2bfloat16(a);
    p.y = __float2bfloat16(b);
    return *(uint32_t*)&p;
}
// swizzled byte offset within a 128row x 64B tile (rows of 4 x 16B groups)
__device__ __forceinline__ uint32_t sw_off(int row, int g) {
    return (uint32_t)(((row << 2) | (g ^ ((row >> 1) & 3))) << 4);
}

// ---------------------------------------------------------------------------
// Weight conversion kernels
// ---------------------------------------------------------------------------
__global__ void convw_t(const float* __restrict__ W, bf16* __restrict__ hi,
                        bf16* __restrict__ lo, int K, int N) {
    __shared__ float t[32][33];
    int kb = blockIdx.x * 32, nb = blockIdx.y * 32;
    int tx = threadIdx.x, ty = threadIdx.y;     // 32 x 8
#pragma unroll
    for (int i = 0; i < 32; i += 8) t[ty + i][tx] = W[(size_t)(kb + ty + i) * N + nb + tx];
    __syncthreads();
#pragma unroll
    for (int i = 0; i < 32; i += 8) {
        float v = t[tx][ty + i];
        size_t o = (size_t)(nb + ty + i) * K + kb + tx;
        bf16 h, l; split_bf16(v, h, l);
        hi[o] = h; lo[o] = l;
    }
}
// QKV weights [H, D, HD] -> [N=H*HD, K=D]
__global__ void convw_qkv(const float* __restrict__ W, bf16* __restrict__ hi,
                          bf16* __restrict__ lo) {
    __shared__ float t[32][33];
    int h = blockIdx.z;
    int db = blockIdx.x * 32, eb = blockIdx.y * 32;
    const float* base = W + (size_t)h * D_ * HD_;
    int tx = threadIdx.x, ty = threadIdx.y;
#pragma unroll
    for (int i = 0; i < 32; i += 8) t[ty + i][tx] = base[(size_t)(db + ty + i) * HD_ + eb + tx];
    __syncthreads();
#pragma unroll
    for (int i = 0; i < 32; i += 8) {
        float v = t[tx][ty + i];
        int n = h * HD_ + eb + ty + i, k = db + tx;
        bf16 hh, ll; split_bf16(v, hh, ll);
        hi[(size_t)n * D_ + k] = hh; lo[(size_t)n * D_ + k] = ll;
    }
}
__global__ void pack_bias(const float* __restrict__ bq, const float* __restrict__ bk,
                          const float* __restrict__ bv, float* __restrict__ o) {
    int t = blockIdx.x * 256 + threadIdx.x;
    if (t < D_) { o[t] = bq[t]; o[t + D_] = bk[t]; o[t + 2 * D_] = bv[t]; }
}

// ---------------------------------------------------------------------------
// LayerNorm -> bf16 hi/lo pair. One block per row, 256 threads.
// ---------------------------------------------------------------------------
__global__ void ln_kernel(const float* __restrict__ x, const float* __restrict__ g,
                          const float* __restrict__ be, bf16* __restrict__ hi,
                          bf16* __restrict__ lo) {
    int row = blockIdx.x;
    int t = threadIdx.x;
    const float* xr = x + (size_t)row * D_;
    float v0 = xr[t], v1 = xr[t + 256];
    float s = v0 + v1, ss = v0 * v0 + v1 * v1;
#pragma unroll
    for (int o = 16; o > 0; o >>= 1) {
        s  += __shfl_xor_sync(0xffffffffu, s, o);
        ss += __shfl_xor_sync(0xffffffffu, ss, o);
    }
    __shared__ float rs[8], rss[8];
    if ((t & 31) == 0) { rs[t >> 5] = s; rss[t >> 5] = ss; }
    __syncthreads();
    s = 0.f; ss = 0.f;
#pragma unroll
    for (int i = 0; i < 8; i++) { s += rs[i]; ss += rss[i]; }
    float mean = s * (1.f / (float)D_);
    float var  = ss * (1.f / (float)D_) - mean * mean;
    float r = rsqrtf(var + 1e-5f);
    float y0 = (v0 - mean) * r * g[t] + be[t];
    float y1 = (v1 - mean) * r * g[t + 256] + be[t + 256];
    bf16 h, l;
    split_bf16(y0, h, l); hi[(size_t)row * D_ + t] = h;       lo[(size_t)row * D_ + t] = l;
    split_bf16(y1, h, l); hi[(size_t)row * D_ + t + 256] = h; lo[(size_t)row * D_ + t + 256] = l;
}

// ---------------------------------------------------------------------------
// mma.sync GEMM with bf16x3 compensation + cp.async double buffering.
// MODE 0: fp32 out (+res). MODE 1: bf16 pair out (RELU opt). MODE 2: qkv
// scatter — bf16 pairs to head-major [which][b][h][s][hd].
// ---------------------------------------------------------------------------
#define SMT_AHI 0
#define SMT_ALO 8192
#define SMT_BHI 16384
#define SMT_BLO 24576
#define GSTAGE  32768
#define GEMM_SMEM (2*GSTAGE)

template <int MODE, bool RELU, bool RES>
__global__ void __launch_bounds__(256, 2) mma_gemm(
    const bf16* __restrict__ Ahi, const bf16* __restrict__ Alo,
    const bf16* __restrict__ Bhi, const bf16* __restrict__ Blo,
    const float* __restrict__ bias, const float* __restrict__ res,
    float* __restrict__ Cf, bf16* __restrict__ Chi, bf16* __restrict__ Clo,
    int M, int N, int K) {
    extern __shared__ __align__(128) char smem_buf[];
    uint32_t sb = smem_to_u32(smem_buf);
    int tid = threadIdx.x, lane = tid & 31, wid = tid >> 5;
    int wm = wid >> 2, wn = wid & 3;
    int m0 = blockIdx.y * 128, n0 = blockIdx.x * 128;

    float acc[4][4][4];
#pragma unroll
    for (int a = 0; a < 4; a++)
#pragma unroll
        for (int b = 0; b < 4; b++)
#pragma unroll
            for (int cc = 0; cc < 4; cc++) acc[a][b][cc] = 0.f;

    int ldrow = tid >> 2, ldg_ = tid & 3;
    int nchunk = K >> 5;

    auto issue = [&](int c, int st) {
        int k0 = c << 5;
        uint32_t base = sb + (uint32_t)st * GSTAGE;
#pragma unroll
        for (int it = 0; it < 2; it++) {
            int row = ldrow + it * 64;
            uint32_t off = sw_off(row, ldg_);
            size_t ao = (size_t)(m0 + row) * K + k0 + ldg_ * 8;
            size_t bo = (size_t)(n0 + row) * K + k0 + ldg_ * 8;
            cp16(base + SMT_AHI + off, Ahi + ao);
            cp16(base + SMT_ALO + off, Alo + ao);
            cp16(base + SMT_BHI + off, Bhi + bo);
            cp16(base + SMT_BLO + off, Blo + bo);
        }
    };

    issue(0, 0);
    CP_COMMIT();
    for (int c = 0; c < nchunk; c++) {
        int st = c & 1;
        if (c + 1 < nchunk) { issue(c + 1, (c + 1) & 1); CP_COMMIT(); CP_WAIT1(); }
        else CP_WAIT0();
        __syncthreads();
        uint32_t base = sb + (uint32_t)st * GSTAGE;
#pragma unroll
        for (int ks = 0; ks < 2; ks++) {
            int kg = ks * 2;
            uint32_t bh[4][2], bl[4][2];
#pragma unroll
            for (int ntp = 0; ntp < 2; ntp++) {
                int nrow = wn * 32 + ntp * 16 + (lane & 7) + ((lane >> 4) & 1) * 8;
                int bg = kg + ((lane >> 3) & 1);
                uint32_t off = sw_off(nrow, bg);
                uint32_t t4[4];
                ldsm_x4(t4, base + SMT_BHI + off);
                bh[ntp * 2][0] = t4[0]; bh[ntp * 2][1] = t4[1];
                bh[ntp * 2 + 1][0] = t4[2]; bh[ntp * 2 + 1][1] = t4[3];
                ldsm_x4(t4, base + SMT_BLO + off);
                bl[ntp * 2][0] = t4[0]; bl[ntp * 2][1] = t4[1];
                bl[ntp * 2 + 1][0] = t4[2]; bl[ntp * 2 + 1][1] = t4[3];
            }
#pragma unroll
            for (int mt = 0; mt < 4; mt++) {
                int arow = wm * 64 + mt * 16 + (lane & 7) + ((lane >> 3) & 1) * 8;
                int ag = kg + (lane >> 4);
                uint32_t off = sw_off(arow, ag);
                uint32_t ah[4], al[4];
                ldsm_x4(ah, base + SMT_AHI + off);
                ldsm_x4(al, base + SMT_ALO + off);
#pragma unroll
                for (int nt = 0; nt < 4; nt++) {
                    mma16816(acc[mt][nt], ah, bh[nt]);
                    mma16816(acc[mt][nt], ah, bl[nt]);
                    mma16816(acc[mt][nt], al, bh[nt]);
                }
            }
        }
        __syncthreads();
    }

#pragma unroll
    for (int mt = 0; mt < 4; mt++) {
#pragma unroll
        for (int nt = 0; nt < 4; nt++) {
            int r0 = m0 + wm * 64 + mt * 16 + (lane >> 2);
            int col = n0 + wn * 32 + nt * 8 + (lane & 3) * 2;
            float b0 = __ldg(bias + col), b1 = __ldg(bias + col + 1);
            float v00 = acc[mt][nt][0] + b0, v01 = acc[mt][nt][1] + b1;
            float v10 = acc[mt][nt][2] + b0, v11 = acc[mt][nt][3] + b1;
            if (RELU) {
                v00 = fmaxf(v00, 0.f); v01 = fmaxf(v01, 0.f);
                v10 = fmaxf(v10, 0.f); v11 = fmaxf(v11, 0.f);
            }
            if (MODE == 0) {
                if (RES) {
                    float2 ra = *(const float2*)(res + (size_t)r0 * N + col);
                    float2 rb = *(const float2*)(res + (size_t)(r0 + 8) * N + col);
                    v00 += ra.x; v01 += ra.y; v10 += rb.x; v11 += rb.y;
                }
                float2 o0 = {v00, v01}, o1 = {v10, v11};
                *(float2*)(Cf + (size_t)r0 * N + col) = o0;
                *(float2*)(Cf + (size_t)(r0 + 8) * N + col) = o1;
            } else if (MODE == 1) {
                bf16 h, l;
                __nv_bfloat162 ph, pl;
                split_bf16(v00, h, l); ph.x = h; pl.x = l;
                split_bf16(v01, h, l); ph.y = h; pl.y = l;
                *(__nv_bfloat162*)(Chi + (size_t)r0 * N + col) = ph;
                *(__nv_bfloat162*)(Clo + (size_t)r0 * N + col) = pl;
                split_bf16(v10, h, l); ph.x = h; pl.x = l;
                split_bf16(v11, h, l); ph.y = h; pl.y = l;
                *(__nv_bfloat162*)(Chi + (size_t)(r0 + 8) * N + col) = ph;
                *(__nv_bfloat162*)(Clo + (size_t)(r0 + 8) * N + col) = pl;
            } else {
                // qkv scatter: head-major
                int which = col >> 9, rem = col & 511;
                int hh2 = rem >> 6, e = rem & 63;
#pragma unroll
                for (int rr = 0; rr < 2; rr++) {
                    int t = r0 + rr * 8;
                    float va = rr ? v10 : v00, vb = rr ? v11 : v01;
                    size_t off = (size_t)which * (T_ * (size_t)D_) +
                                 (((size_t)(t >> 11) * H_ + hh2) * S_ + (t & (S_ - 1))) * HD_ + e;
                    bf16 h, l;
                    __nv_bfloat162 ph, pl;
                    split_bf16(va, h, l); ph.x = h; pl.x = l;
                    split_bf16(vb, h, l); ph.y = h; pl.y = l;
                    *(__nv_bfloat162*)(Chi + off) = ph;
                    *(__nv_bfloat162*)(Clo + off) = pl;
                }
            }
        }
    }
}

// ---------------------------------------------------------------------------
// Flash attention on tensor cores, bf16x3. Inputs are bf16 hi/lo pairs in
// head-major layout -> pure cp.async byte copies, double-buffered K/V tiles.
// Q-tile 64 rows (4 warps x m16), KV-tile 64, HD=64. 128 threads.
// ---------------------------------------------------------------------------
#define FPAD 72                          // bf16 per row (144 B)
#define FTILE (64*FPAD*2)                // 9216 B per tile
#define FSTAGE (4*FTILE)                 // K_HI,K_LO,V_HI,V_LO
#define FLASH_SMEM (2*FSTAGE)            // 73728 B

__global__ void __launch_bounds__(128) flash_mma_kernel(
    const bf16* __restrict__ Phi, const bf16* __restrict__ Plo,
    bf16* __restrict__ Ohi, bf16* __restrict__ Olo) {
    extern __shared__ __align__(16) char fsm[];
    uint32_t sb = smem_to_u32(fsm);
    int tid = threadIdx.x, lane = tid & 31, wid = tid >> 5;
    int bh = blockIdx.y;
    int b_ = bh >> 3, h = bh & 7;
    int q0 = blockIdx.x * 64;

    size_t headoff = ((size_t)(b_ * H_ + h) * S_) * HD_;
    const bf16* Qh = Phi + headoff + (size_t)q0 * HD_;
    const bf16* Ql = Plo + headoff + (size_t)q0 * HD_;
    const bf16* Kh = Phi + (size_t)T_ * D_ + headoff;
    const bf16* Kl = Plo + (size_t)T_ * D_ + headoff;
    const bf16* Vh = Phi + 2 * (size_t)T_ * D_ + headoff;
    const bf16* Vl = Plo + 2 * (size_t)T_ * D_ + headoff;

    // --- stage Q in buf0 (plain copies), extract fragments ---
#pragma unroll
    for (int it = 0; it < 4; it++) {
        int idx = it * 128 + tid;          // 0..511
        int row = idx >> 3, fg = idx & 7;
        uint32_t off = (uint32_t)(row * (FPAD * 2) + fg * 16);
        *(uint4*)(fsm + off)         = *(const uint4*)(Qh + (size_t)row * HD_ + fg * 8);
        *(uint4*)(fsm + FTILE + off) = *(const uint4*)(Ql + (size_t)row * HD_ + fg * 8);
    }
    __syncthreads();
    uint32_t qh[4][4], ql[4][4];
    {
        int arow = wid * 16 + (lane & 7) + ((lane >> 3) & 1) * 8;
#pragma unroll
        for (int ks = 0; ks < 4; ks++) {
            uint32_t off = (uint32_t)(arow * (FPAD * 2) + (ks * 2 + (lane >> 4)) * 16);
            ldsm_x4(qh[ks], sb + off);
            ldsm_x4(ql[ks], sb + FTILE + off);
        }
    }
    __syncthreads();

    auto issueKV = [&](int kv, int st) {
        uint32_t bs = sb + (uint32_t)st * FSTAGE;
#pragma unroll
        for (int it = 0; it < 4; it++) {
            int idx = it * 128 + tid;
            int row = idx >> 3, fg = idx & 7;
            uint32_t off = (uint32_t)(row * (FPAD * 2) + fg * 16);
            size_t go = (size_t)(kv + row) * HD_ + fg * 8;
            cp16(bs + off,             Kh + go);
            cp16(bs + FTILE + off,     Kl + go);
            cp16(bs + 2 * FTILE + off, Vh + go);
            cp16(bs + 3 * FTILE + off, Vl + go);
        }
    };

    float m0 = -1e30f, m1 = -1e30f, l0 = 0.f, l1 = 0.f;
    float oacc[8][4];
#pragma unroll
    for (int i = 0; i < 8; i++)
#pragma unroll
        for (int j = 0; j < 4; j++) oacc[i][j] = 0.f;

    issueKV(0, 0);
    CP_COMMIT();
    int ntile = S_ / 64;
    for (int ti = 0; ti < ntile; ti++) {
        int st = ti & 1;
        if (ti + 1 < ntile) { issueKV((ti + 1) * 64, (ti + 1) & 1); CP_COMMIT(); CP_WAIT1(); }
        else CP_WAIT0();
        __syncthreads();
        uint32_t bs = sb + (uint32_t)st * FSTAGE;

        // --- S = Q K^T (8 n-tiles), bf16x3 ---
        float sacc[8][4];
#pragma unroll
        for (int i = 0; i < 8; i++)
#pragma unroll
            for (int j = 0; j < 4; j++) sacc[i][j] = 0.f;

#pragma unroll
        for (int ng = 0; ng < 4; ng++) {
            int nrow = ng * 16 + (lane & 7) + ((lane >> 4) & 1) * 8;
#pragma unroll
            for (int ks = 0; ks < 4; ks++) {
                int bg = ks * 2 + ((lane >> 3) & 1);
                uint32_t off = (uint32_t)(nrow * (FPAD * 2) + bg * 16);
                uint32_t th[4], tl[4];
                ldsm_x4(th, bs + off);
                ldsm_x4(tl, bs + FTILE + off);
                uint32_t bh0[2] = {th[0], th[1]}, bh1[2] = {th[2], th[3]};
                uint32_t bl0[2] = {tl[0], tl[1]}, bl1[2] = {tl[2], tl[3]};
                mma16816(sacc[ng * 2],     qh[ks], bh0);
                mma16816(sacc[ng * 2],     qh[ks], bl0);
                mma16816(sacc[ng * 2],     ql[ks], bh0);
                mma16816(sacc[ng * 2 + 1], qh[ks], bh1);
                mma16816(sacc[ng * 2 + 1], qh[ks], bl1);
                mma16816(sacc[ng * 2 + 1], ql[ks], bh1);
            }
        }

        // --- online softmax ---
        float rmax0 = -1e30f, rmax1 = -1e30f;
#pragma unroll
        for (int nt = 0; nt < 8; nt++) {
            rmax0 = fmaxf(rmax0, fmaxf(sacc[nt][0], sacc[nt][1]));
            rmax1 = fmaxf(rmax1, fmaxf(sacc[nt][2], sacc[nt][3]));
        }
        rmax0 = fmaxf(rmax0, __shfl_xor_sync(0xffffffffu, rmax0, 1));
        rmax0 = fmaxf(rmax0, __shfl_xor_sync(0xffffffffu, rmax0, 2));
        rmax1 = fmaxf(rmax1, __shfl_xor_sync(0xffffffffu, rmax1, 1));
        rmax1 = fmaxf(rmax1, __shfl_xor_sync(0xffffffffu, rmax1, 2));
        float mn0 = fmaxf(m0, rmax0), mn1 = fmaxf(m1, rmax1);
        float corr0 = __expf(m0 - mn0), corr1 = __expf(m1 - mn1);
        float ps0 = 0.f, ps1 = 0.f;
#pragma unroll
        for (int nt = 0; nt < 8; nt++) {
            sacc[nt][0] = __expf(sacc[nt][0] - mn0);
            sacc[nt][1] = __expf(sacc[nt][1] - mn0);
            sacc[nt][2] = __expf(sacc[nt][2] - mn1);
            sacc[nt][3] = __expf(sacc[nt][3] - mn1);
            ps0 += sacc[nt][0] + sacc[nt][1];
            ps1 += sacc[nt][2] + sacc[nt][3];
        }
        ps0 += __shfl_xor_sync(0xffffffffu, ps0, 1);
        ps0 += __shfl_xor_sync(0xffffffffu, ps0, 2);
        ps1 += __shfl_xor_sync(0xffffffffu, ps1, 1);
        ps1 += __shfl_xor_sync(0xffffffffu, ps1, 2);
        l0 = l0 * corr0 + ps0; l1 = l1 * corr1 + ps1;
        m0 = mn0; m1 = mn1;
#pragma unroll
        for (int i = 0; i < 8; i++) {
            oacc[i][0] *= corr0; oacc[i][1] *= corr0;
            oacc[i][2] *= corr1; oacc[i][3] *= corr1;
        }

        // --- O += P V (P from registers) ---
#pragma unroll
        for (int kc = 0; kc < 4; kc++) {
            float* pa = sacc[kc * 2];
            float* pb = sacc[kc * 2 + 1];
            uint32_t phi[4], plo[4];
            phi[0] = pack_bf2(pa[0], pa[1]);
            phi[1] = pack_bf2(pa[2], pa[3]);
            phi[2] = pack_bf2(pb[0], pb[1]);
            phi[3] = pack_bf2(pb[2], pb[3]);
            {
                __nv_bfloat162 h0 = *(__nv_bfloat162*)&phi[0];
                __nv_bfloat162 h1 = *(__nv_bfloat162*)&phi[1];
                __nv_bfloat162 h2 = *(__nv_bfloat162*)&phi[2];
                __nv_bfloat162 h3 = *(__nv_bfloat162*)&phi[3];
                plo[0] = pack_bf2(pa[0] - __bfloat162float(h0.x), pa[1] - __bfloat162float(h0.y));
                plo[1] = pack_bf2(pa[2] - __bfloat162float(h1.x), pa[3] - __bfloat162float(h1.y));
                plo[2] = pack_bf2(pb[0] - __bfloat162float(h2.x), pb[1] - __bfloat162float(h2.y));
                plo[3] = pack_bf2(pb[2] - __bfloat162float(h3.x), pb[3] - __bfloat162float(h3.y));
            }
#pragma unroll
            for (int hg = 0; hg < 4; hg++) {
                int vrow = kc * 16 + ((lane >> 3) & 1) * 8 + (lane & 7);
                int vcol = hg * 16 + ((lane >> 4) & 1) * 8;
                uint32_t off = (uint32_t)(vrow * (FPAD * 2) + vcol * 2);
                uint32_t th[4], tl[4];
                ldsm_x4_t(th, bs + 2 * FTILE + off);
                ldsm_x4_t(tl, bs + 3 * FTILE + off);
                uint32_t bh0[2] = {th[0], th[1]}, bh1[2] = {th[2], th[3]};
                uint32_t bl0[2] = {tl[0], tl[1]}, bl1[2] = {tl[2], tl[3]};
                mma16816(oacc[hg * 2],     phi, bh0);
                mma16816(oacc[hg * 2],     phi, bl0);
                mma16816(oacc[hg * 2],     plo, bh0);
                mma16816(oacc[hg * 2 + 1], phi, bh1);
                mma16816(oacc[hg * 2 + 1], phi, bl1);
                mma16816(oacc[hg * 2 + 1], plo, bh1);
            }
        }
        __syncthreads();
    }

    // --- write O as bf16 hi/lo pairs in [B,S,D] concat layout ---
    float inv0 = 1.f / l0, inv1 = 1.f / l1;
    int r0 = q0 + wid * 16 + (lane >> 2);
#pragma unroll
    for (int nt = 0; nt < 8; nt++) {
        int col = h * HD_ + nt * 8 + (lane & 3) * 2;
        float v00 = oacc[nt][0] * inv0, v01 = oacc[nt][1] * inv0;
        float v10 = oacc[nt][2] * inv1, v11 = oacc[nt][3] * inv1;
        bf16 hh, ll;
        __nv_bfloat162 ph, pl;
        split_bf16(v00, hh, ll); ph.x = hh; pl.x = ll;
        split_bf16(v01, hh, ll); ph.y = hh; pl.y = ll;
        *(__nv_bfloat162*)(Ohi + ((size_t)b_ * S_ + r0) * D_ + col) = ph;
        *(__nv_bfloat162*)(Olo + ((size_t)b_ * S_ + r0) * D_ + col) = pl;
        split_bf16(v10, hh, ll); ph.x = hh; pl.x = ll;
        split_bf16(v11, hh, ll); ph.y = hh; pl.y = ll;
        *(__nv_bfloat162*)(Ohi + ((size_t)b_ * S_ + r0 + 8) * D_ + col) = ph;
        *(__nv_bfloat162*)(Olo + ((size_t)b_ * S_ + r0 + 8) * D_ + col) = pl;
    }
}

// ---------------------------------------------------------------------------
// Launch
// ---------------------------------------------------------------------------
extern "C" void kernel_launch(void* const* d_in, const int* in_sizes, int n_in,
                              void* d_out, int out_size) {
    const float* x   = (const float*)d_in[0];
    const float* Wq  = (const float*)d_in[1];
    const float* bq  = (const float*)d_in[2];
    const float* Wk  = (const float*)d_in[3];
    const float* bk  = (const float*)d_in[4];
    const float* Wv  = (const float*)d_in[5];
    const float* bv  = (const float*)d_in[6];
    const float* Wp  = (const float*)d_in[7];
    const float* bp  = (const float*)d_in[8];
    const float* W1  = (const float*)d_in[9];
    const float* b1  = (const float*)d_in[10];
    const float* W2  = (const float*)d_in[11];
    const float* b2  = (const float*)d_in[12];
    const float* g1  = (const float*)d_in[13];
    const float* be1 = (const float*)d_in[14];
    const float* g2  = (const float*)d_in[15];
    const float* be2 = (const float*)d_in[16];
    float* out = (float*)d_out;

    bf16 *xn_hi, *xn_lo, *attn_hi, *attn_lo, *h_hi, *h_lo, *qb_hi, *qb_lo;
    bf16 *wqkv_hi, *wqkv_lo, *wp_hi, *wp_lo, *w1_hi, *w1_lo, *w2_hi, *w2_lo;
    float *bqkv;
    cudaGetSymbolAddress((void**)&xn_hi, g_xn_hi);     cudaGetSymbolAddress((void**)&xn_lo, g_xn_lo);
    cudaGetSymbolAddress((void**)&attn_hi, g_attn_hi); cudaGetSymbolAddress((void**)&attn_lo, g_attn_lo);
    cudaGetSymbolAddress((void**)&h_hi, g_h_hi);       cudaGetSymbolAddress((void**)&h_lo, g_h_lo);
    cudaGetSymbolAddress((void**)&qb_hi, g_qkvb_hi);   cudaGetSymbolAddress((void**)&qb_lo, g_qkvb_lo);
    cudaGetSymbolAddress((void**)&wqkv_hi, g_wqkv_hi); cudaGetSymbolAddress((void**)&wqkv_lo, g_wqkv_lo);
    cudaGetSymbolAddress((void**)&wp_hi, g_wp_hi);     cudaGetSymbolAddress((void**)&wp_lo, g_wp_lo);
    cudaGetSymbolAddress((void**)&w1_hi, g_w1_hi);     cudaGetSymbolAddress((void**)&w1_lo, g_w1_lo);
    cudaGetSymbolAddress((void**)&w2_hi, g_w2_hi);     cudaGetSymbolAddress((void**)&w2_lo, g_w2_lo);
    cudaGetSymbolAddress((void**)&bqkv, g_bqkv);

    cudaFuncSetAttribute(mma_gemm<2, false, false>, cudaFuncAttributeMaxDynamicSharedMemorySize, GEMM_SMEM);
    cudaFuncSetAttribute(mma_gemm<0, false, true>,  cudaFuncAttributeMaxDynamicSharedMemorySize, GEMM_SMEM);
    cudaFuncSetAttribute(mma_gemm<1, true, false>,  cudaFuncAttributeMaxDynamicSharedMemorySize, GEMM_SMEM);
    cudaFuncSetAttribute(flash_mma_kernel, cudaFuncAttributeMaxDynamicSharedMemorySize, FLASH_SMEM);

    dim3 tb(32, 8);
    convw_qkv<<<dim3(D_ / 32, HD_ / 32, H_), tb>>>(Wq, wqkv_hi,               wqkv_lo);
    convw_qkv<<<dim3(D_ / 32, HD_ / 32, H_), tb>>>(Wk, wqkv_hi + D_ * D_,     wqkv_lo + D_ * D_);
    convw_qkv<<<dim3(D_ / 32, HD_ / 32, H_), tb>>>(Wv, wqkv_hi + 2 * D_ * D_, wqkv_lo + 2 * D_ * D_);
    convw_t<<<dim3(D_ / 32, D_ / 32), tb>>>(Wp, wp_hi, wp_lo, D_, D_);
    convw_t<<<dim3(D_ / 32, FF_ / 32), tb>>>(W1, w1_hi, w1_lo, D_, FF_);
    convw_t<<<dim3(FF_ / 32, D_ / 32), tb>>>(W2, w2_hi, w2_lo, FF_, D_);
    pack_bias<<<2, 256>>>(bq, bk, bv, bqkv);

    // LN1
    ln_kernel<<<T_, 256>>>(x, g1, be1, xn_hi, xn_lo);

    // fused QKV GEMM -> bf16 pairs, head-major scatter
    mma_gemm<2, false, false><<<dim3(QKV_N / 128, T_ / 128), 256, GEMM_SMEM>>>(
        xn_hi, xn_lo, wqkv_hi, wqkv_lo, bqkv, nullptr, nullptr, qb_hi, qb_lo, T_, QKV_N, D_);

    // flash attention (tensor cores, bf16 in/out)
    flash_mma_kernel<<<dim3(S_ / 64, B_ * H_), 128, FLASH_SMEM>>>(qb_hi, qb_lo, attn_hi, attn_lo);

    // proj + residual: out = x + attn @ Wp + bp
    mma_gemm<0, false, true><<<dim3(D_ / 128, T_ / 128), 256, GEMM_SMEM>>>(
        attn_hi, attn_lo, wp_hi, wp_lo, bp, x, out, nullptr, nullptr, T_, D_, D_);

    // LN2
    ln_kernel<<<T_, 256>>>(out, g2, be2, xn_hi, xn_lo);

    // MLP1 (ReLU) -> h bf16 pair
    mma_gemm<1, true, false><<<dim3(FF_ / 128, T_ / 128), 256, GEMM_SMEM>>>(
        xn_hi, xn_lo, w1_hi, w1_lo, b1, nullptr, nullptr, h_hi, h_lo, T_, FF_, D_);

    // MLP2 + residual (in place on out)
    mma_gemm<0, false, true><<<dim3(D_ / 128, T_ / 128), 256, GEMM_SMEM>>>(
        h_hi, h_lo, w2_hi, w2_lo, b2, out, out, nullptr, nullptr, T_, D_, FF_);
}